// round 13
// baseline (speedup 1.0000x reference)
#include <cuda_runtime.h>
#include <cuda_fp16.h>
#include <cstdint>
#include <math.h>

#define NN      20000
#define DEG     16
#define TT      3
#define HID     128
#define EPS_SEL 0.01f
#define SC_M    256
#define GH_M    384
#define NBLK    313            // ceil(20000/64)

// ---------------- device scratch ----------------
__device__ float g_SC [(size_t)NN * SC_M];
__device__ float g_G  [(size_t)NN * GH_M];
__device__ float g_GH [(size_t)NN * GH_M];
__device__ __align__(16) __half g_vh [(size_t)NN * 128];   // node_attr hi/lo split
__device__ __align__(16) __half g_vl [(size_t)NN * 128];
__device__ __align__(16) __half g_hAh[(size_t)NN * HID];
__device__ __align__(16) __half g_hAl[(size_t)NN * HID];
__device__ __align__(16) __half g_hBh[(size_t)NN * HID];
__device__ __align__(16) __half g_hBl[(size_t)NN * HID];
__device__ int   g_sel[TT * NN];
__device__ float g_Bsc_t[SC_M * 128];
__device__ float g_bias_sc[SC_M];
__device__ __align__(16) __half g_Wih_h[GH_M * 128], g_Wih_l[GH_M * 128];
__device__ __align__(16) __half g_Whh_h[GH_M * 128], g_Whh_l[GH_M * 128];
__device__ __align__(16) __half g_Wout_h[128 * 128], g_Wout_l[128 * 128];

__device__ __forceinline__ uint32_t smem_u32(const void* p) {
    uint32_t a;
    asm("{ .reg .u64 t; cvta.to.shared.u64 t, %1; cvt.u32.u64 %0, t; }" : "=r"(a) : "l"(p));
    return a;
}
__device__ __forceinline__ uint32_t f2tf32(float x) {
    uint32_t r;
    asm("cvt.rna.tf32.f32 %0, %1;" : "=r"(r) : "f"(x));
    return r;
}
#define CP16(dst, src) \
    asm volatile("cp.async.cg.shared.global [%0], [%1], 16;" :: "r"(dst), "l"(src))
#define CP_COMMIT() asm volatile("cp.async.commit_group;" ::: "memory")
#define CP_WAIT(n)  asm volatile("cp.async.wait_group %0;" :: "n"(n) : "memory")

// ---------------- weight prep ----------------
__global__ void prep_weights(const float* __restrict__ W1, const float* __restrict__ b1,
                             const float* __restrict__ Wih, const float* __restrict__ Whh,
                             const float* __restrict__ Wout) {
    int i = blockIdx.x * blockDim.x + threadIdx.x;
    if (i < SC_M * 128) {
        int j = i / 128, k = i % 128;
        int s = j >> 6, m = j & 63;
        g_Bsc_t[i] = W1[(size_t)(s * 128 + k) * 64 + m];
        if (k == 0) g_bias_sc[j] = (j < 64) ? b1[j] : 0.0f;
        return;
    }
    int i2 = i - SC_M * 128;
    float w;
    __half *dh, *dl;
    if (i2 < GH_M * 128) { w = Wih[i2]; dh = g_Wih_h; dl = g_Wih_l; }
    else if (i2 < 2 * GH_M * 128) { i2 -= GH_M * 128; w = Whh[i2]; dh = g_Whh_h; dl = g_Whh_l; }
    else {
        i2 -= 2 * GH_M * 128;
        if (i2 >= 128 * 128) return;
        int n = i2 / 128, k = i2 % 128;
        w = Wout[(size_t)k * 128 + n];
        dh = g_Wout_h; dl = g_Wout_l;
    }
    __half hi = __float2half_rn(w);
    dh[i2] = hi;
    dl[i2] = __float2half_rn(w - __half2float(hi));
}

// ---------------- node_attr hi/lo split ----------------
__global__ void split_attr(const float* __restrict__ A) {
    int i = (blockIdx.x * blockDim.x + threadIdx.x) * 4;
    if (i >= NN * 128) return;
    float4 a = *(const float4*)(A + i);
    float av[4] = {a.x, a.y, a.z, a.w};
    __half hv[4], lv[4];
#pragma unroll
    for (int q = 0; q < 4; q++) {
        hv[q] = __float2half_rn(av[q]);
        lv[q] = __float2half_rn(av[q] - __half2float(hv[q]));
    }
    *(uint2*)(g_vh + i) = *(uint2*)hv;
    *(uint2*)(g_vl + i) = *(uint2*)lv;
}

// ================= pipelined GEMM constants (2 x 64-k chunks, 2 stages) =================
#define HLDS 72
#define SA_H 0
#define SA_L (64 * HLDS * 2)
#define SB_H (2 * 64 * HLDS * 2)
#define SB_L (SB_H + 128 * HLDS * 2)
#define STAGE_BYTES (SB_L + 128 * HLDS * 2)      // 55296
#define PIPE_SMEM (2 * STAGE_BYTES)              // 110592

// pipelined fp16x2-split 64x128 GEMM tile body — 512 threads, 16 warps (4x4), warp tile 16x32
__device__ __forceinline__ void pipe_gemm_body(const __half* __restrict__ Ah,
                                               const __half* __restrict__ Al,
                                               const __half* __restrict__ bh,
                                               const __half* __restrict__ bl,
                                               const float* __restrict__ bias,
                                               float* __restrict__ C, int rows, int ldc,
                                               int rowBase, int colBase,
                                               char* smem) {
    uint32_t sb = smem_u32(smem);
    int tid = threadIdx.x;
    int lane = tid & 31;
    int wid = tid >> 5;
    int wm = wid >> 2, wn = wid & 3;

#pragma unroll
    for (int kc = 0; kc < 2; kc++) {
        uint32_t stage = sb + kc * STAGE_BYTES;
        int kof = kc * 64;
        {
            int idx = tid;                       // 0..511
            int r = idx >> 3, j = (idx & 7) * 8;
            int gr = rowBase + r;
            if (gr >= rows) gr = rows - 1;
            uint32_t off = (uint32_t)((r * HLDS + j) * 2);
            CP16(stage + SA_H + off, Ah + (size_t)gr * 128 + kof + j);
            CP16(stage + SA_L + off, Al + (size_t)gr * 128 + kof + j);
        }
#pragma unroll
        for (int i = 0; i < 2; i++) {
            int idx = tid + 512 * i;             // 0..1023
            int r = idx >> 3, j = (idx & 7) * 8;
            uint32_t off = (uint32_t)((r * HLDS + j) * 2);
            CP16(stage + SB_H + off, bh + (size_t)r * 128 + kof + j);
            CP16(stage + SB_L + off, bl + (size_t)r * 128 + kof + j);
        }
        CP_COMMIT();
    }

    float acc[4][4];
#pragma unroll
    for (int ni = 0; ni < 4; ni++)
#pragma unroll
        for (int q = 0; q < 4; q++) acc[ni][q] = 0.0f;

    int a_r = lane & 15, a_c = (lane >> 4) * 8;
    int b_r = (lane & 7) + ((lane >> 4) << 3), b_c = ((lane >> 3) & 1) * 8;

#pragma unroll
    for (int kc = 0; kc < 2; kc++) {
        if (kc == 0) { CP_WAIT(1); } else { CP_WAIT(0); }
        __syncthreads();
        uint32_t stage = sb + kc * STAGE_BYTES;
        const uint32_t aOffT[3] = {stage + SA_H, stage + SA_H, stage + SA_L};
        const uint32_t bOffT[3] = {stage + SB_H, stage + SB_L, stage + SB_H};
#pragma unroll
        for (int term = 0; term < 3; term++) {
            uint32_t abase = aOffT[term], bbase = bOffT[term];
#pragma unroll
            for (int k0 = 0; k0 < 4; k0++) {
                int kk = k0 * 16;
                uint32_t af[4];
                uint32_t addr = abase + (uint32_t)(((wm * 16 + a_r) * HLDS + kk + a_c) * 2);
                asm volatile("ldmatrix.sync.aligned.m8n8.x4.shared.b16 {%0,%1,%2,%3}, [%4];"
                             : "=r"(af[0]), "=r"(af[1]), "=r"(af[2]), "=r"(af[3]) : "r"(addr));
                uint32_t bf[4][2];
#pragma unroll
                for (int nj = 0; nj < 2; nj++) {
                    uint32_t ba = bbase + (uint32_t)(((wn * 32 + nj * 16 + b_r) * HLDS + kk + b_c) * 2);
                    uint32_t r0, r1, r2, r3;
                    asm volatile("ldmatrix.sync.aligned.m8n8.x4.shared.b16 {%0,%1,%2,%3}, [%4];"
                                 : "=r"(r0), "=r"(r1), "=r"(r2), "=r"(r3) : "r"(ba));
                    bf[2 * nj][0] = r0; bf[2 * nj][1] = r1;
                    bf[2 * nj + 1][0] = r2; bf[2 * nj + 1][1] = r3;
                }
#pragma unroll
                for (int ni = 0; ni < 4; ni++)
                    asm volatile(
                        "mma.sync.aligned.m16n8k16.row.col.f32.f16.f16.f32 "
                        "{%0,%1,%2,%3}, {%4,%5,%6,%7}, {%8,%9}, {%0,%1,%2,%3};"
                        : "+f"(acc[ni][0]), "+f"(acc[ni][1]), "+f"(acc[ni][2]), "+f"(acc[ni][3])
                        : "r"(af[0]), "r"(af[1]), "r"(af[2]), "r"(af[3]),
                          "r"(bf[ni][0]), "r"(bf[ni][1]));
            }
        }
    }

    int rb = rowBase + wm * 16;
    int cb = colBase + wn * 32;
#pragma unroll
    for (int ni = 0; ni < 4; ni++) {
        int r0 = rb + (lane >> 2);
        int c0 = cb + ni * 8 + (lane & 3) * 2;
        float bv0 = bias[c0], bv1 = bias[c0 + 1];
        if (r0 < rows)
            *(float2*)(C + (size_t)r0 * ldc + c0) =
                make_float2(acc[ni][0] + bv0, acc[ni][1] + bv1);
        if (r0 + 8 < rows)
            *(float2*)(C + (size_t)(r0 + 8) * ldc + c0) =
                make_float2(acc[ni][2] + bv0, acc[ni][3] + bv1);
    }
}

// ================= fused projection kernel — 512 threads =================
#define SLDS 132
__global__ __launch_bounds__(512, 2) void proj_all(const float* __restrict__ A,
                                                   const float* __restrict__ bih, int rows) {
    extern __shared__ __align__(16) char smem[];
    int tid = threadIdx.x;
    int lane = tid & 31;
    int wid = tid >> 5;
    int rowBase = blockIdx.y * 64;

    if (blockIdx.x >= 2) {
        int bx = blockIdx.x - 2;
        pipe_gemm_body(g_vh, g_vl,
                       g_Wih_h + (size_t)bx * 128 * 128, g_Wih_l + (size_t)bx * 128 * 128,
                       bih, g_G, rows, GH_M, rowBase, bx * 128, smem);
        return;
    }

    // ---------- tf32 scoring path (selection-critical), 16 warps 4x4, warp tile 16x32 ----------
    float* As = (float*)smem;
    float* Bs = As + 64 * SLDS;
    int colBase = blockIdx.x * 128;
    for (int c = tid; c < 2048; c += 512) {
        int r = c >> 5, k = (c & 31) * 4;
        int gr = rowBase + r;
        float4 a = make_float4(0.f, 0.f, 0.f, 0.f);
        if (gr < rows) a = *(const float4*)(A + (size_t)gr * 128 + k);
        *(float4*)(As + r * SLDS + k) = a;
    }
    for (int c = tid; c < 4096; c += 512) {
        int r = c >> 5, k = (c & 31) * 4;
        *(float4*)(Bs + r * SLDS + k) =
            *(const float4*)(g_Bsc_t + (size_t)(colBase + r) * 128 + k);
    }
    __syncthreads();

    int wm = wid >> 2, wn = wid & 3;
    int m0 = wm * 16, n0 = wn * 32;
    int gid = lane >> 2, tig = lane & 3;
    float acc[4][4];
#pragma unroll
    for (int ni = 0; ni < 4; ni++)
#pragma unroll
        for (int q = 0; q < 4; q++) acc[ni][q] = 0.0f;

#pragma unroll
    for (int k0 = 0; k0 < 16; k0++) {
        int kk = k0 * 8;
        float av[4] = {As[(m0 + gid) * SLDS + kk + tig],
                       As[(m0 + gid + 8) * SLDS + kk + tig],
                       As[(m0 + gid) * SLDS + kk + tig + 4],
                       As[(m0 + gid + 8) * SLDS + kk + tig + 4]};
        uint32_t ah[4], al[4];
#pragma unroll
        for (int q = 0; q < 4; q++) {
            ah[q] = f2tf32(av[q]);
            al[q] = f2tf32(av[q] - __uint_as_float(ah[q]));
        }
#pragma unroll
        for (int nf = 0; nf < 4; nf++) {
            float b0 = Bs[(n0 + nf * 8 + gid) * SLDS + kk + tig];
            float b1 = Bs[(n0 + nf * 8 + gid) * SLDS + kk + tig + 4];
            uint32_t bh0 = f2tf32(b0), bh1 = f2tf32(b1);
            uint32_t bl0 = f2tf32(b0 - __uint_as_float(bh0));
            uint32_t bl1 = f2tf32(b1 - __uint_as_float(bh1));
            asm volatile(
                "mma.sync.aligned.m16n8k8.row.col.f32.tf32.tf32.f32 "
                "{%0,%1,%2,%3}, {%4,%5,%6,%7}, {%8,%9}, {%0,%1,%2,%3};"
                : "+f"(acc[nf][0]), "+f"(acc[nf][1]), "+f"(acc[nf][2]), "+f"(acc[nf][3])
                : "r"(ah[0]), "r"(ah[1]), "r"(ah[2]), "r"(ah[3]), "r"(bh0), "r"(bh1));
            asm volatile(
                "mma.sync.aligned.m16n8k8.row.col.f32.tf32.tf32.f32 "
                "{%0,%1,%2,%3}, {%4,%5,%6,%7}, {%8,%9}, {%0,%1,%2,%3};"
                : "+f"(acc[nf][0]), "+f"(acc[nf][1]), "+f"(acc[nf][2]), "+f"(acc[nf][3])
                : "r"(ah[0]), "r"(ah[1]), "r"(ah[2]), "r"(ah[3]), "r"(bl0), "r"(bl1));
            asm volatile(
                "mma.sync.aligned.m16n8k8.row.col.f32.tf32.tf32.f32 "
                "{%0,%1,%2,%3}, {%4,%5,%6,%7}, {%8,%9}, {%0,%1,%2,%3};"
                : "+f"(acc[nf][0]), "+f"(acc[nf][1]), "+f"(acc[nf][2]), "+f"(acc[nf][3])
                : "r"(al[0]), "r"(al[1]), "r"(al[2]), "r"(al[3]), "r"(bh0), "r"(bh1));
        }
    }
    int rb = rowBase + m0;
#pragma unroll
    for (int nf = 0; nf < 4; nf++) {
        int c0 = colBase + n0 + nf * 8 + tig * 2;
        float bv0 = g_bias_sc[c0], bv1 = g_bias_sc[c0 + 1];
#pragma unroll
        for (int half = 0; half < 2; half++) {
            int r0 = rb + gid + half * 8;
            if (r0 >= rows) continue;
            *(float2*)(g_SC + (size_t)r0 * SC_M + c0) =
                make_float2(acc[nf][2 * half] + bv0, acc[nf][2 * half + 1] + bv1);
        }
    }
}

// ================= walk (3 steps) — unchanged =================
#define WALK_BLKS ((NN * 32 + 255) / 256)
__global__ __launch_bounds__(256) void walk3(const int* __restrict__ dst,
                                             const float* __restrict__ W2,
                                             const float* __restrict__ b2p,
                                             const float* __restrict__ noise) {
    const unsigned FULL = 0xFFFFFFFFu;
    int tid = threadIdx.x;
    int gwarp = (blockIdx.x * 256 + tid) >> 5;
    int lane = tid & 31;
    int wz = tid >> 5;
    __shared__ float s_logp[8][16];
    if (gwarp >= NN) return;
    int n = gwarp;
    int q = lane & 15;
    int h = lane >> 4;

    float4 bse = *(const float4*)(g_SC + (size_t)n * SC_M + q * 4);
    float4 w2 = *(const float4*)(W2 + q * 4);
    float b2 = b2p[0];
    int cur = n;

#pragma unroll
    for (int t = 0; t < TT; t++) {
        const int* nb = dst + (size_t)cur * DEG;
        const int slot = (1 + t) * 64;
#pragma unroll
        for (int it = 0; it < 8; it++) {
            int d = it * 2 + h;
            int cand = nb[d];
            float4 c = *(const float4*)(g_SC + (size_t)cand * SC_M + slot + q * 4);
            float s = fmaxf(bse.x + c.x, 0.f) * w2.x + fmaxf(bse.y + c.y, 0.f) * w2.y +
                      fmaxf(bse.z + c.z, 0.f) * w2.z + fmaxf(bse.w + c.w, 0.f) * w2.w;
#pragma unroll
            for (int off = 8; off >= 1; off >>= 1)
                s += __shfl_xor_sync(FULL, s, off);
            if (q == 0) s_logp[wz][d] = s + b2;
        }
        __syncwarp();
        float lp = (lane < DEG) ? s_logp[wz][lane] : -1e38f;
        float m = lp;
#pragma unroll
        for (int off = 8; off >= 1; off >>= 1)
            m = fmaxf(m, __shfl_xor_sync(FULL, m, off));
        float e = (lane < DEG) ? expf(lp - m) : 0.0f;
        float ssum = e;
#pragma unroll
        for (int off = 8; off >= 1; off >>= 1)
            ssum += __shfl_xor_sync(FULL, ssum, off);
        float norm = m + logf(ssum);
        float p = (lane < DEG)
                      ? expf(lp - norm) + EPS_SEL * noise[((size_t)t * NN + n) * DEG + lane]
                      : -1e38f;
        float bv = p;
        int bi = lane;
#pragma unroll
        for (int off = 8; off >= 1; off >>= 1) {
            float ov = __shfl_xor_sync(FULL, bv, off);
            int oi = __shfl_xor_sync(FULL, bi, off);
            if (ov > bv || (ov == bv && oi < bi)) { bv = ov; bi = oi; }
        }
        int bsel = __shfl_sync(FULL, bi, 0);
        int csel = nb[bsel];
        float4 c = *(const float4*)(g_SC + (size_t)csel * SC_M + slot + q * 4);
        bse.x += c.x; bse.y += c.y; bse.z += c.z; bse.w += c.w;
        cur = csel;
        if (lane == 0) g_sel[t * NN + n] = csel;
        __syncwarp();
    }
}

// ================= gru0 (h_prev = 0) — unchanged =================
#define GRU0_BLKS ((NN * 32 + 255) / 256)
__global__ __launch_bounds__(256) void gru0(const float* __restrict__ bhh) {
    int gt = blockIdx.x * 256 + threadIdx.x;
    int n = gt >> 5, c4 = (gt & 31) * 4;
    if (n >= NN) return;
    const float* gi = g_G + (size_t)n * GH_M;
    float4 gir = *(const float4*)(gi + c4);
    float4 giz = *(const float4*)(gi + 128 + c4);
    float4 gin = *(const float4*)(gi + 256 + c4);
    float4 br = *(const float4*)(bhh + c4);
    float4 bz = *(const float4*)(bhh + 128 + c4);
    float4 bn = *(const float4*)(bhh + 256 + c4);
    float o[4];
    {
        float r = 1.0f / (1.0f + expf(-(gir.x + br.x)));
        float z = 1.0f / (1.0f + expf(-(giz.x + bz.x)));
        o[0] = (1.0f - z) * tanhf(gin.x + r * bn.x);
    }
    {
        float r = 1.0f / (1.0f + expf(-(gir.y + br.y)));
        float z = 1.0f / (1.0f + expf(-(giz.y + bz.y)));
        o[1] = (1.0f - z) * tanhf(gin.y + r * bn.y);
    }
    {
        float r = 1.0f / (1.0f + expf(-(gir.z + br.z)));
        float z = 1.0f / (1.0f + expf(-(giz.z + bz.z)));
        o[2] = (1.0f - z) * tanhf(gin.z + r * bn.z);
    }
    {
        float r = 1.0f / (1.0f + expf(-(gir.w + br.w)));
        float z = 1.0f / (1.0f + expf(-(giz.w + bz.w)));
        o[3] = (1.0f - z) * tanhf(gin.w + r * bn.w);
    }
    __half hv[4], lv[4];
#pragma unroll
    for (int q = 0; q < 4; q++) {
        hv[q] = __float2half_rn(o[q]);
        lv[q] = __float2half_rn(o[q] - __half2float(hv[q]));
    }
    *(uint2*)(g_hAh + (size_t)n * HID + c4) = *(uint2*)hv;
    *(uint2*)(g_hAl + (size_t)n * HID + c4) = *(uint2*)lv;
}

// ================= pipelined GEMM kernel — 512 threads =================
__global__ __launch_bounds__(512, 2) void mma_gemm_h(const __half* __restrict__ Ah,
                                                     const __half* __restrict__ Al,
                                                     const __half* __restrict__ Bh,
                                                     const __half* __restrict__ Bl,
                                                     const float* __restrict__ bias,
                                                     float* __restrict__ C, int rows, int ldc) {
    extern __shared__ __align__(16) char smem[];
    pipe_gemm_body(Ah, Al,
                   Bh + (size_t)blockIdx.x * 128 * 128, Bl + (size_t)blockIdx.x * 128 * 128,
                   bias, C, rows, ldc, blockIdx.y * 64, blockIdx.x * 128, smem);
}

// ================= GRU elementwise gates (unchanged) =================
__global__ __launch_bounds__(256) void gru_elem(const __half* __restrict__ hinh,
                                                const __half* __restrict__ hinl,
                                                __half* __restrict__ houth,
                                                __half* __restrict__ houtl, int step) {
    int gt = blockIdx.x * blockDim.x + threadIdx.x;
    int n = gt >> 5, c4 = (gt & 31) * 4;
    if (n >= NN) return;
    int src = g_sel[(step - 1) * NN + n];
    const float* gi = g_G + (size_t)src * GH_M;
    const float* gh = g_GH + (size_t)n * GH_M;
    float4 gir = *(const float4*)(gi + c4);
    float4 giz = *(const float4*)(gi + 128 + c4);
    float4 gin = *(const float4*)(gi + 256 + c4);
    float4 ghr = *(const float4*)(gh + c4);
    float4 ghz = *(const float4*)(gh + 128 + c4);
    float4 ghn = *(const float4*)(gh + 256 + c4);
    uint2 hpu = *(const uint2*)(hinh + (size_t)n * HID + c4);
    uint2 hlu = *(const uint2*)(hinl + (size_t)n * HID + c4);
    __half* hph = (__half*)&hpu;
    __half* hpl = (__half*)&hlu;
    float o[4];
    float gir_a[4] = {gir.x, gir.y, gir.z, gir.w};
    float giz_a[4] = {giz.x, giz.y, giz.z, giz.w};
    float gin_a[4] = {gin.x, gin.y, gin.z, gin.w};
    float ghr_a[4] = {ghr.x, ghr.y, ghr.z, ghr.w};
    float ghz_a[4] = {ghz.x, ghz.y, ghz.z, ghz.w};
    float ghn_a[4] = {ghn.x, ghn.y, ghn.z, ghn.w};
#pragma unroll
    for (int q = 0; q < 4; q++) {
        float hp = __half2float(hph[q]) + __half2float(hpl[q]);
        float r = 1.0f / (1.0f + expf(-(gir_a[q] + ghr_a[q])));
        float z = 1.0f / (1.0f + expf(-(giz_a[q] + ghz_a[q])));
        o[q] = (1.0f - z) * tanhf(gin_a[q] + r * ghn_a[q]) + z * hp;
    }
    __half hv[4], lv[4];
#pragma unroll
    for (int q = 0; q < 4; q++) {
        hv[q] = __float2half_rn(o[q]);
        lv[q] = __float2half_rn(o[q] - __half2float(hv[q]));
    }
    *(uint2*)(houth + (size_t)n * HID + c4) = *(uint2*)hv;
    *(uint2*)(houtl + (size_t)n * HID + c4) = *(uint2*)lv;
}

// ---------------- host launch ----------------
extern "C" void kernel_launch(void* const* d_in, const int* in_sizes, int n_in,
                              void* d_out, int out_size) {
    const float* node_attr = (const float*)d_in[0];
    const int*   edge_idx  = (const int*)d_in[1];
    const float* W1   = (const float*)d_in[3];
    const float* b1   = (const float*)d_in[4];
    const float* W2   = (const float*)d_in[5];
    const float* b2   = (const float*)d_in[6];
    const float* Wih  = (const float*)d_in[7];
    const float* Whh  = (const float*)d_in[8];
    const float* bih  = (const float*)d_in[9];
    const float* bhh  = (const float*)d_in[10];
    const float* Wout = (const float*)d_in[11];
    const float* bout = (const float*)d_in[12];
    const float* noise = (const float*)d_in[13];
    float* out = (float*)d_out;
    const int* dst = edge_idx + (size_t)NN * DEG;

    float *pGH;
    __half *pHAh, *pHAl, *pHBh, *pHBl, *pWhhH, *pWhhL, *pWoutH, *pWoutL;
    cudaGetSymbolAddress((void**)&pGH, g_GH);
    cudaGetSymbolAddress((void**)&pHAh, g_hAh);
    cudaGetSymbolAddress((void**)&pHAl, g_hAl);
    cudaGetSymbolAddress((void**)&pHBh, g_hBh);
    cudaGetSymbolAddress((void**)&pHBl, g_hBl);
    cudaGetSymbolAddress((void**)&pWhhH, g_Whh_h);
    cudaGetSymbolAddress((void**)&pWhhL, g_Whh_l);
    cudaGetSymbolAddress((void**)&pWoutH, g_Wout_h);
    cudaGetSymbolAddress((void**)&pWoutL, g_Wout_l);

    static bool init_done = false;
    static cudaStream_t s1;
    static cudaEvent_t evS, evSp, evP, evW;
    if (!init_done) {
        cudaFuncSetAttribute(proj_all, cudaFuncAttributeMaxDynamicSharedMemorySize, PIPE_SMEM);
        cudaFuncSetAttribute(mma_gemm_h, cudaFuncAttributeMaxDynamicSharedMemorySize, PIPE_SMEM);
        cudaStreamCreateWithFlags(&s1, cudaStreamNonBlocking);
        cudaEventCreateWithFlags(&evS, cudaEventDisableTiming);
        cudaEventCreateWithFlags(&evSp, cudaEventDisableTiming);
        cudaEventCreateWithFlags(&evP, cudaEventDisableTiming);
        cudaEventCreateWithFlags(&evW, cudaEventDisableTiming);
        init_done = true;
    }

    const int EBLK = (NN * 32 + 255) / 256;   // 2500

    // fork: split_attr on s1 || prep_weights on 0
    cudaEventRecord(evS, 0);
    cudaStreamWaitEvent(s1, evS, 0);
    split_attr<<<(NN * 128 / 4 + 255) / 256, 256, 0, s1>>>(node_attr);
    {
        int total = SC_M * 128 + 2 * GH_M * 128 + 128 * 128;
        prep_weights<<<(total + 255) / 256, 256>>>(W1, b1, Wih, Whh, Wout);
    }
    cudaEventRecord(evSp, s1);
    cudaStreamWaitEvent(0, evSp, 0);

    // proj (needs prep + split)
    proj_all<<<dim3(5, NBLK), 512, PIPE_SMEM>>>(node_attr, bih, NN);

    // fork: walk3 on s1 || (gru0 -> GEMM1) on 0
    cudaEventRecord(evP, 0);
    cudaStreamWaitEvent(s1, evP, 0);
    walk3<<<WALK_BLKS, 256, 0, s1>>>(dst, W2, b2, noise);
    gru0<<<GRU0_BLKS, 256>>>(bhh);
    mma_gemm_h<<<dim3(3, NBLK), 512, PIPE_SMEM>>>(pHAh, pHAl, pWhhH, pWhhL, bhh, pGH, NN, GH_M);
    cudaEventRecord(evW, s1);
    cudaStreamWaitEvent(0, evW, 0);

    // join: sequential GRU chain on 0
    gru_elem<<<EBLK, 256>>>(pHAh, pHAl, pHBh, pHBl, 1);
    mma_gemm_h<<<dim3(3, NBLK), 512, PIPE_SMEM>>>(pHBh, pHBl, pWhhH, pWhhL, bhh, pGH, NN, GH_M);
    gru_elem<<<EBLK, 256>>>(pHBh, pHBl, pHAh, pHAl, 2);
    mma_gemm_h<<<dim3(3, NBLK), 512, PIPE_SMEM>>>(pHAh, pHAl, pWhhH, pWhhL, bhh, pGH, NN, GH_M);
    gru_elem<<<EBLK, 256>>>(pHAh, pHAl, pHBh, pHBl, 3);
    mma_gemm_h<<<dim3(1, NBLK), 512, PIPE_SMEM>>>(pHBh, pHBl, pWoutH, pWoutL, bout, out, NN, HID);
}

// round 14
// speedup vs baseline: 1.2353x; 1.2353x over previous
#include <cuda_runtime.h>
#include <cuda_fp16.h>
#include <cstdint>
#include <math.h>

#define NN      20000
#define DEG     16
#define TT      3
#define HID     128
#define EPS_SEL 0.01f
#define SC_M    256
#define GH_M    384
#define NBLK    313            // ceil(20000/64)

// ---------------- device scratch ----------------
__device__ float g_SC [(size_t)NN * SC_M];
__device__ float g_G  [(size_t)NN * GH_M];
__device__ float g_GH [(size_t)NN * GH_M];
__device__ __align__(16) __half g_vh [(size_t)NN * 128];   // node_attr hi/lo split
__device__ __align__(16) __half g_vl [(size_t)NN * 128];
__device__ __align__(16) __half g_hAh[(size_t)NN * HID];
__device__ __align__(16) __half g_hAl[(size_t)NN * HID];
__device__ __align__(16) __half g_hBh[(size_t)NN * HID];
__device__ __align__(16) __half g_hBl[(size_t)NN * HID];
__device__ int   g_sel[TT * NN];
__device__ float g_Bsc_t[SC_M * 128];
__device__ float g_bias_sc[SC_M];
__device__ __align__(16) __half g_Wih_h[GH_M * 128], g_Wih_l[GH_M * 128];
__device__ __align__(16) __half g_Whh_h[GH_M * 128], g_Whh_l[GH_M * 128];
__device__ __align__(16) __half g_Wout_h[128 * 128], g_Wout_l[128 * 128];

__device__ __forceinline__ uint32_t smem_u32(const void* p) {
    uint32_t a;
    asm("{ .reg .u64 t; cvta.to.shared.u64 t, %1; cvt.u32.u64 %0, t; }" : "=r"(a) : "l"(p));
    return a;
}
__device__ __forceinline__ uint32_t f2tf32(float x) {
    uint32_t r;
    asm("cvt.rna.tf32.f32 %0, %1;" : "=r"(r) : "f"(x));
    return r;
}
#define CP16(dst, src) \
    asm volatile("cp.async.cg.shared.global [%0], [%1], 16;" :: "r"(dst), "l"(src))
#define CP_COMMIT() asm volatile("cp.async.commit_group;" ::: "memory")
#define CP_WAIT(n)  asm volatile("cp.async.wait_group %0;" :: "n"(n) : "memory")

// ---------------- weight prep ----------------
__global__ void prep_weights(const float* __restrict__ W1, const float* __restrict__ b1,
                             const float* __restrict__ Wih, const float* __restrict__ Whh,
                             const float* __restrict__ Wout) {
    int i = blockIdx.x * blockDim.x + threadIdx.x;
    if (i < SC_M * 128) {
        int j = i / 128, k = i % 128;
        int s = j >> 6, m = j & 63;
        g_Bsc_t[i] = W1[(size_t)(s * 128 + k) * 64 + m];
        if (k == 0) g_bias_sc[j] = (j < 64) ? b1[j] : 0.0f;
        return;
    }
    int i2 = i - SC_M * 128;
    float w;
    __half *dh, *dl;
    if (i2 < GH_M * 128) { w = Wih[i2]; dh = g_Wih_h; dl = g_Wih_l; }
    else if (i2 < 2 * GH_M * 128) { i2 -= GH_M * 128; w = Whh[i2]; dh = g_Whh_h; dl = g_Whh_l; }
    else {
        i2 -= 2 * GH_M * 128;
        if (i2 >= 128 * 128) return;
        int n = i2 / 128, k = i2 % 128;
        w = Wout[(size_t)k * 128 + n];
        dh = g_Wout_h; dl = g_Wout_l;
    }
    __half hi = __float2half_rn(w);
    dh[i2] = hi;
    dl[i2] = __float2half_rn(w - __half2float(hi));
}

// ---------------- node_attr hi/lo split ----------------
__global__ void split_attr(const float* __restrict__ A) {
    int i = (blockIdx.x * blockDim.x + threadIdx.x) * 4;
    if (i >= NN * 128) return;
    float4 a = *(const float4*)(A + i);
    float av[4] = {a.x, a.y, a.z, a.w};
    __half hv[4], lv[4];
#pragma unroll
    for (int q = 0; q < 4; q++) {
        hv[q] = __float2half_rn(av[q]);
        lv[q] = __float2half_rn(av[q] - __half2float(hv[q]));
    }
    *(uint2*)(g_vh + i) = *(uint2*)hv;
    *(uint2*)(g_vl + i) = *(uint2*)lv;
}

// ================= pipelined GEMM constants (2 x 64-k chunks, 2 stages) =================
#define HLDS 72
#define SA_H 0
#define SA_L (64 * HLDS * 2)
#define SB_H (2 * 64 * HLDS * 2)
#define SB_L (SB_H + 128 * HLDS * 2)
#define STAGE_BYTES (SB_L + 128 * HLDS * 2)      // 55296
#define PIPE_SMEM (2 * STAGE_BYTES)              // 110592

// pipelined fp16x2-split 64x128 GEMM tile body — 256 threads, 8 warps (2x4), warp tile 32x32
__device__ __forceinline__ void pipe_gemm_body(const __half* __restrict__ Ah,
                                               const __half* __restrict__ Al,
                                               const __half* __restrict__ bh,
                                               const __half* __restrict__ bl,
                                               const float* __restrict__ bias,
                                               float* __restrict__ C, int rows, int ldc,
                                               int rowBase, int colBase,
                                               char* smem) {
    uint32_t sb = smem_u32(smem);
    int tid = threadIdx.x;
    int lane = tid & 31;
    int wid = tid >> 5;
    int wm = wid >> 2, wn = wid & 3;   // 2 x 4 warps

#pragma unroll
    for (int kc = 0; kc < 2; kc++) {
        uint32_t stage = sb + kc * STAGE_BYTES;
        int kof = kc * 64;
#pragma unroll
        for (int i = 0; i < 2; i++) {
            int idx = tid + 256 * i;
            int r = idx >> 3, j = (idx & 7) * 8;
            int gr = rowBase + r;
            if (gr >= rows) gr = rows - 1;
            uint32_t off = (uint32_t)((r * HLDS + j) * 2);
            CP16(stage + SA_H + off, Ah + (size_t)gr * 128 + kof + j);
            CP16(stage + SA_L + off, Al + (size_t)gr * 128 + kof + j);
        }
#pragma unroll
        for (int i = 0; i < 4; i++) {
            int idx = tid + 256 * i;
            int r = idx >> 3, j = (idx & 7) * 8;
            uint32_t off = (uint32_t)((r * HLDS + j) * 2);
            CP16(stage + SB_H + off, bh + (size_t)r * 128 + kof + j);
            CP16(stage + SB_L + off, bl + (size_t)r * 128 + kof + j);
        }
        CP_COMMIT();
    }

    float acc[2][4][4];
#pragma unroll
    for (int mi = 0; mi < 2; mi++)
#pragma unroll
        for (int ni = 0; ni < 4; ni++)
#pragma unroll
            for (int q = 0; q < 4; q++) acc[mi][ni][q] = 0.0f;

    int a_r = lane & 15, a_c = (lane >> 4) * 8;
    int b_r = (lane & 7) + ((lane >> 4) << 3), b_c = ((lane >> 3) & 1) * 8;

#pragma unroll
    for (int kc = 0; kc < 2; kc++) {
        if (kc == 0) { CP_WAIT(1); } else { CP_WAIT(0); }
        __syncthreads();
        uint32_t stage = sb + kc * STAGE_BYTES;
        const uint32_t aOffT[3] = {stage + SA_H, stage + SA_H, stage + SA_L};
        const uint32_t bOffT[3] = {stage + SB_H, stage + SB_L, stage + SB_H};
#pragma unroll
        for (int term = 0; term < 3; term++) {
            uint32_t abase = aOffT[term], bbase = bOffT[term];
#pragma unroll
            for (int k0 = 0; k0 < 4; k0++) {
                int kk = k0 * 16;
                uint32_t af[2][4];
#pragma unroll
                for (int mi = 0; mi < 2; mi++) {
                    uint32_t addr = abase +
                        (uint32_t)(((wm * 32 + mi * 16 + a_r) * HLDS + kk + a_c) * 2);
                    asm volatile("ldmatrix.sync.aligned.m8n8.x4.shared.b16 {%0,%1,%2,%3}, [%4];"
                                 : "=r"(af[mi][0]), "=r"(af[mi][1]),
                                   "=r"(af[mi][2]), "=r"(af[mi][3]) : "r"(addr));
                }
                uint32_t bf[4][2];
#pragma unroll
                for (int nj = 0; nj < 2; nj++) {
                    uint32_t ba = bbase +
                        (uint32_t)(((wn * 32 + nj * 16 + b_r) * HLDS + kk + b_c) * 2);
                    uint32_t r0, r1, r2, r3;
                    asm volatile("ldmatrix.sync.aligned.m8n8.x4.shared.b16 {%0,%1,%2,%3}, [%4];"
                                 : "=r"(r0), "=r"(r1), "=r"(r2), "=r"(r3) : "r"(ba));
                    bf[2 * nj][0] = r0; bf[2 * nj][1] = r1;
                    bf[2 * nj + 1][0] = r2; bf[2 * nj + 1][1] = r3;
                }
#pragma unroll
                for (int mi = 0; mi < 2; mi++)
#pragma unroll
                    for (int ni = 0; ni < 4; ni++)
                        asm volatile(
                            "mma.sync.aligned.m16n8k16.row.col.f32.f16.f16.f32 "
                            "{%0,%1,%2,%3}, {%4,%5,%6,%7}, {%8,%9}, {%0,%1,%2,%3};"
                            : "+f"(acc[mi][ni][0]), "+f"(acc[mi][ni][1]),
                              "+f"(acc[mi][ni][2]), "+f"(acc[mi][ni][3])
                            : "r"(af[mi][0]), "r"(af[mi][1]), "r"(af[mi][2]), "r"(af[mi][3]),
                              "r"(bf[ni][0]), "r"(bf[ni][1]));
            }
        }
    }

    int cb = colBase + wn * 32;
#pragma unroll
    for (int mi = 0; mi < 2; mi++) {
        int rb = rowBase + wm * 32 + mi * 16;
#pragma unroll
        for (int ni = 0; ni < 4; ni++) {
            int r0 = rb + (lane >> 2);
            int c0 = cb + ni * 8 + (lane & 3) * 2;
            float bv0 = bias[c0], bv1 = bias[c0 + 1];
            if (r0 < rows)
                *(float2*)(C + (size_t)r0 * ldc + c0) =
                    make_float2(acc[mi][ni][0] + bv0, acc[mi][ni][1] + bv1);
            if (r0 + 8 < rows)
                *(float2*)(C + (size_t)(r0 + 8) * ldc + c0) =
                    make_float2(acc[mi][ni][2] + bv0, acc[mi][ni][3] + bv1);
        }
    }
}

// ================= fused projection kernel — 256 threads (R12 structure) =================
#define SLDS 132
__global__ __launch_bounds__(256, 2) void proj_all(const float* __restrict__ A,
                                                   const float* __restrict__ bih, int rows) {
    extern __shared__ __align__(16) char smem[];
    int tid = threadIdx.x;
    int lane = tid & 31;
    int wid = tid >> 5;
    int rowBase = blockIdx.y * 64;

    if (blockIdx.x >= 2) {
        int bx = blockIdx.x - 2;
        pipe_gemm_body(g_vh, g_vl,
                       g_Wih_h + (size_t)bx * 128 * 128, g_Wih_l + (size_t)bx * 128 * 128,
                       bih, g_G, rows, GH_M, rowBase, bx * 128, smem);
        return;
    }

    // ---------- tf32 scoring path (selection-critical, unchanged R12) ----------
    float* As = (float*)smem;
    float* Bs = As + 64 * SLDS;
    int colBase = blockIdx.x * 128;
    for (int c = tid; c < 2048; c += 256) {
        int r = c >> 5, k = (c & 31) * 4;
        int gr = rowBase + r;
        float4 a = make_float4(0.f, 0.f, 0.f, 0.f);
        if (gr < rows) a = *(const float4*)(A + (size_t)gr * 128 + k);
        *(float4*)(As + r * SLDS + k) = a;
    }
    for (int c = tid; c < 4096; c += 256) {
        int r = c >> 5, k = (c & 31) * 4;
        *(float4*)(Bs + r * SLDS + k) =
            *(const float4*)(g_Bsc_t + (size_t)(colBase + r) * 128 + k);
    }
    __syncthreads();

    int wm = wid >> 1, wn = wid & 1;
    int m0 = wm * 16, n0 = wn * 64;
    int gid = lane >> 2, tig = lane & 3;
    float acc[8][4];
#pragma unroll
    for (int ni = 0; ni < 8; ni++)
#pragma unroll
        for (int q = 0; q < 4; q++) acc[ni][q] = 0.0f;

#pragma unroll
    for (int k0 = 0; k0 < 16; k0++) {
        int kk = k0 * 8;
        float av[4] = {As[(m0 + gid) * SLDS + kk + tig],
                       As[(m0 + gid + 8) * SLDS + kk + tig],
                       As[(m0 + gid) * SLDS + kk + tig + 4],
                       As[(m0 + gid + 8) * SLDS + kk + tig + 4]};
        uint32_t ah[4], al[4];
#pragma unroll
        for (int q = 0; q < 4; q++) {
            ah[q] = f2tf32(av[q]);
            al[q] = f2tf32(av[q] - __uint_as_float(ah[q]));
        }
#pragma unroll
        for (int nf = 0; nf < 8; nf++) {
            float b0 = Bs[(n0 + nf * 8 + gid) * SLDS + kk + tig];
            float b1 = Bs[(n0 + nf * 8 + gid) * SLDS + kk + tig + 4];
            uint32_t bh0 = f2tf32(b0), bh1 = f2tf32(b1);
            uint32_t bl0 = f2tf32(b0 - __uint_as_float(bh0));
            uint32_t bl1 = f2tf32(b1 - __uint_as_float(bh1));
            asm volatile(
                "mma.sync.aligned.m16n8k8.row.col.f32.tf32.tf32.f32 "
                "{%0,%1,%2,%3}, {%4,%5,%6,%7}, {%8,%9}, {%0,%1,%2,%3};"
                : "+f"(acc[nf][0]), "+f"(acc[nf][1]), "+f"(acc[nf][2]), "+f"(acc[nf][3])
                : "r"(ah[0]), "r"(ah[1]), "r"(ah[2]), "r"(ah[3]), "r"(bh0), "r"(bh1));
            asm volatile(
                "mma.sync.aligned.m16n8k8.row.col.f32.tf32.tf32.f32 "
                "{%0,%1,%2,%3}, {%4,%5,%6,%7}, {%8,%9}, {%0,%1,%2,%3};"
                : "+f"(acc[nf][0]), "+f"(acc[nf][1]), "+f"(acc[nf][2]), "+f"(acc[nf][3])
                : "r"(ah[0]), "r"(ah[1]), "r"(ah[2]), "r"(ah[3]), "r"(bl0), "r"(bl1));
            asm volatile(
                "mma.sync.aligned.m16n8k8.row.col.f32.tf32.tf32.f32 "
                "{%0,%1,%2,%3}, {%4,%5,%6,%7}, {%8,%9}, {%0,%1,%2,%3};"
                : "+f"(acc[nf][0]), "+f"(acc[nf][1]), "+f"(acc[nf][2]), "+f"(acc[nf][3])
                : "r"(al[0]), "r"(al[1]), "r"(al[2]), "r"(al[3]), "r"(bh0), "r"(bh1));
        }
    }
    int rb = rowBase + m0;
#pragma unroll
    for (int nf = 0; nf < 8; nf++) {
        int c0 = colBase + n0 + nf * 8 + tig * 2;
        float bv0 = g_bias_sc[c0], bv1 = g_bias_sc[c0 + 1];
#pragma unroll
        for (int half = 0; half < 2; half++) {
            int r0 = rb + gid + half * 8;
            if (r0 >= rows) continue;
            *(float2*)(g_SC + (size_t)r0 * SC_M + c0) =
                make_float2(acc[nf][2 * half] + bv0, acc[nf][2 * half + 1] + bv1);
        }
    }
}

// ================= walk (3 steps) — unchanged =================
#define WALK_BLKS ((NN * 32 + 255) / 256)
__global__ __launch_bounds__(256) void walk3(const int* __restrict__ dst,
                                             const float* __restrict__ W2,
                                             const float* __restrict__ b2p,
                                             const float* __restrict__ noise) {
    const unsigned FULL = 0xFFFFFFFFu;
    int tid = threadIdx.x;
    int gwarp = (blockIdx.x * 256 + tid) >> 5;
    int lane = tid & 31;
    int wz = tid >> 5;
    __shared__ float s_logp[8][16];
    if (gwarp >= NN) return;
    int n = gwarp;
    int q = lane & 15;
    int h = lane >> 4;

    float4 bse = *(const float4*)(g_SC + (size_t)n * SC_M + q * 4);
    float4 w2 = *(const float4*)(W2 + q * 4);
    float b2 = b2p[0];
    int cur = n;

#pragma unroll
    for (int t = 0; t < TT; t++) {
        const int* nb = dst + (size_t)cur * DEG;
        const int slot = (1 + t) * 64;
#pragma unroll
        for (int it = 0; it < 8; it++) {
            int d = it * 2 + h;
            int cand = nb[d];
            float4 c = *(const float4*)(g_SC + (size_t)cand * SC_M + slot + q * 4);
            float s = fmaxf(bse.x + c.x, 0.f) * w2.x + fmaxf(bse.y + c.y, 0.f) * w2.y +
                      fmaxf(bse.z + c.z, 0.f) * w2.z + fmaxf(bse.w + c.w, 0.f) * w2.w;
#pragma unroll
            for (int off = 8; off >= 1; off >>= 1)
                s += __shfl_xor_sync(FULL, s, off);
            if (q == 0) s_logp[wz][d] = s + b2;
        }
        __syncwarp();
        float lp = (lane < DEG) ? s_logp[wz][lane] : -1e38f;
        float m = lp;
#pragma unroll
        for (int off = 8; off >= 1; off >>= 1)
            m = fmaxf(m, __shfl_xor_sync(FULL, m, off));
        float e = (lane < DEG) ? expf(lp - m) : 0.0f;
        float ssum = e;
#pragma unroll
        for (int off = 8; off >= 1; off >>= 1)
            ssum += __shfl_xor_sync(FULL, ssum, off);
        float norm = m + logf(ssum);
        float p = (lane < DEG)
                      ? expf(lp - norm) + EPS_SEL * noise[((size_t)t * NN + n) * DEG + lane]
                      : -1e38f;
        float bv = p;
        int bi = lane;
#pragma unroll
        for (int off = 8; off >= 1; off >>= 1) {
            float ov = __shfl_xor_sync(FULL, bv, off);
            int oi = __shfl_xor_sync(FULL, bi, off);
            if (ov > bv || (ov == bv && oi < bi)) { bv = ov; bi = oi; }
        }
        int bsel = __shfl_sync(FULL, bi, 0);
        int csel = nb[bsel];
        float4 c = *(const float4*)(g_SC + (size_t)csel * SC_M + slot + q * 4);
        bse.x += c.x; bse.y += c.y; bse.z += c.z; bse.w += c.w;
        cur = csel;
        if (lane == 0) g_sel[t * NN + n] = csel;
        __syncwarp();
    }
}

// ================= gru0 (h_prev = 0) — unchanged =================
#define GRU0_BLKS ((NN * 32 + 255) / 256)
__global__ __launch_bounds__(256) void gru0(const float* __restrict__ bhh) {
    int gt = blockIdx.x * 256 + threadIdx.x;
    int n = gt >> 5, c4 = (gt & 31) * 4;
    if (n >= NN) return;
    const float* gi = g_G + (size_t)n * GH_M;
    float4 gir = *(const float4*)(gi + c4);
    float4 giz = *(const float4*)(gi + 128 + c4);
    float4 gin = *(const float4*)(gi + 256 + c4);
    float4 br = *(const float4*)(bhh + c4);
    float4 bz = *(const float4*)(bhh + 128 + c4);
    float4 bn = *(const float4*)(bhh + 256 + c4);
    float o[4];
    {
        float r = 1.0f / (1.0f + expf(-(gir.x + br.x)));
        float z = 1.0f / (1.0f + expf(-(giz.x + bz.x)));
        o[0] = (1.0f - z) * tanhf(gin.x + r * bn.x);
    }
    {
        float r = 1.0f / (1.0f + expf(-(gir.y + br.y)));
        float z = 1.0f / (1.0f + expf(-(giz.y + bz.y)));
        o[1] = (1.0f - z) * tanhf(gin.y + r * bn.y);
    }
    {
        float r = 1.0f / (1.0f + expf(-(gir.z + br.z)));
        float z = 1.0f / (1.0f + expf(-(giz.z + bz.z)));
        o[2] = (1.0f - z) * tanhf(gin.z + r * bn.z);
    }
    {
        float r = 1.0f / (1.0f + expf(-(gir.w + br.w)));
        float z = 1.0f / (1.0f + expf(-(giz.w + bz.w)));
        o[3] = (1.0f - z) * tanhf(gin.w + r * bn.w);
    }
    __half hv[4], lv[4];
#pragma unroll
    for (int q = 0; q < 4; q++) {
        hv[q] = __float2half_rn(o[q]);
        lv[q] = __float2half_rn(o[q] - __half2float(hv[q]));
    }
    *(uint2*)(g_hAh + (size_t)n * HID + c4) = *(uint2*)hv;
    *(uint2*)(g_hAl + (size_t)n * HID + c4) = *(uint2*)lv;
}

// ================= pipelined GEMM kernel — 256 threads =================
__global__ __launch_bounds__(256, 2) void mma_gemm_h(const __half* __restrict__ Ah,
                                                     const __half* __restrict__ Al,
                                                     const __half* __restrict__ Bh,
                                                     const __half* __restrict__ Bl,
                                                     const float* __restrict__ bias,
                                                     float* __restrict__ C, int rows, int ldc) {
    extern __shared__ __align__(16) char smem[];
    pipe_gemm_body(Ah, Al,
                   Bh + (size_t)blockIdx.x * 128 * 128, Bl + (size_t)blockIdx.x * 128 * 128,
                   bias, C, rows, ldc, blockIdx.y * 64, blockIdx.x * 128, smem);
}

// ================= GRU elementwise gates (unchanged) =================
__global__ __launch_bounds__(256) void gru_elem(const __half* __restrict__ hinh,
                                                const __half* __restrict__ hinl,
                                                __half* __restrict__ houth,
                                                __half* __restrict__ houtl, int step) {
    int gt = blockIdx.x * blockDim.x + threadIdx.x;
    int n = gt >> 5, c4 = (gt & 31) * 4;
    if (n >= NN) return;
    int src = g_sel[(step - 1) * NN + n];
    const float* gi = g_G + (size_t)src * GH_M;
    const float* gh = g_GH + (size_t)n * GH_M;
    float4 gir = *(const float4*)(gi + c4);
    float4 giz = *(const float4*)(gi + 128 + c4);
    float4 gin = *(const float4*)(gi + 256 + c4);
    float4 ghr = *(const float4*)(gh + c4);
    float4 ghz = *(const float4*)(gh + 128 + c4);
    float4 ghn = *(const float4*)(gh + 256 + c4);
    uint2 hpu = *(const uint2*)(hinh + (size_t)n * HID + c4);
    uint2 hlu = *(const uint2*)(hinl + (size_t)n * HID + c4);
    __half* hph = (__half*)&hpu;
    __half* hpl = (__half*)&hlu;
    float o[4];
    float gir_a[4] = {gir.x, gir.y, gir.z, gir.w};
    float giz_a[4] = {giz.x, giz.y, giz.z, giz.w};
    float gin_a[4] = {gin.x, gin.y, gin.z, gin.w};
    float ghr_a[4] = {ghr.x, ghr.y, ghr.z, ghr.w};
    float ghz_a[4] = {ghz.x, ghz.y, ghz.z, ghz.w};
    float ghn_a[4] = {ghn.x, ghn.y, ghn.z, ghn.w};
#pragma unroll
    for (int q = 0; q < 4; q++) {
        float hp = __half2float(hph[q]) + __half2float(hpl[q]);
        float r = 1.0f / (1.0f + expf(-(gir_a[q] + ghr_a[q])));
        float z = 1.0f / (1.0f + expf(-(giz_a[q] + ghz_a[q])));
        o[q] = (1.0f - z) * tanhf(gin_a[q] + r * ghn_a[q]) + z * hp;
    }
    __half hv[4], lv[4];
#pragma unroll
    for (int q = 0; q < 4; q++) {
        hv[q] = __float2half_rn(o[q]);
        lv[q] = __float2half_rn(o[q] - __half2float(hv[q]));
    }
    *(uint2*)(houth + (size_t)n * HID + c4) = *(uint2*)hv;
    *(uint2*)(houtl + (size_t)n * HID + c4) = *(uint2*)lv;
}

// ---------------- host launch ----------------
extern "C" void kernel_launch(void* const* d_in, const int* in_sizes, int n_in,
                              void* d_out, int out_size) {
    const float* node_attr = (const float*)d_in[0];
    const int*   edge_idx  = (const int*)d_in[1];
    const float* W1   = (const float*)d_in[3];
    const float* b1   = (const float*)d_in[4];
    const float* W2   = (const float*)d_in[5];
    const float* b2   = (const float*)d_in[6];
    const float* Wih  = (const float*)d_in[7];
    const float* Whh  = (const float*)d_in[8];
    const float* bih  = (const float*)d_in[9];
    const float* bhh  = (const float*)d_in[10];
    const float* Wout = (const float*)d_in[11];
    const float* bout = (const float*)d_in[12];
    const float* noise = (const float*)d_in[13];
    float* out = (float*)d_out;
    const int* dst = edge_idx + (size_t)NN * DEG;

    float *pGH;
    __half *pHAh, *pHAl, *pHBh, *pHBl, *pWhhH, *pWhhL, *pWoutH, *pWoutL;
    cudaGetSymbolAddress((void**)&pGH, g_GH);
    cudaGetSymbolAddress((void**)&pHAh, g_hAh);
    cudaGetSymbolAddress((void**)&pHAl, g_hAl);
    cudaGetSymbolAddress((void**)&pHBh, g_hBh);
    cudaGetSymbolAddress((void**)&pHBl, g_hBl);
    cudaGetSymbolAddress((void**)&pWhhH, g_Whh_h);
    cudaGetSymbolAddress((void**)&pWhhL, g_Whh_l);
    cudaGetSymbolAddress((void**)&pWoutH, g_Wout_h);
    cudaGetSymbolAddress((void**)&pWoutL, g_Wout_l);

    static bool init_done = false;
    static cudaStream_t s1;
    static cudaEvent_t evS, evSp, evP, evW;
    if (!init_done) {
        cudaFuncSetAttribute(proj_all, cudaFuncAttributeMaxDynamicSharedMemorySize, PIPE_SMEM);
        cudaFuncSetAttribute(mma_gemm_h, cudaFuncAttributeMaxDynamicSharedMemorySize, PIPE_SMEM);
        cudaStreamCreateWithFlags(&s1, cudaStreamNonBlocking);
        cudaEventCreateWithFlags(&evS, cudaEventDisableTiming);
        cudaEventCreateWithFlags(&evSp, cudaEventDisableTiming);
        cudaEventCreateWithFlags(&evP, cudaEventDisableTiming);
        cudaEventCreateWithFlags(&evW, cudaEventDisableTiming);
        init_done = true;
    }

    const int EBLK = (NN * 32 + 255) / 256;   // 2500

    // fork: split_attr on s1 || prep_weights on 0
    cudaEventRecord(evS, 0);
    cudaStreamWaitEvent(s1, evS, 0);
    split_attr<<<(NN * 128 / 4 + 255) / 256, 256, 0, s1>>>(node_attr);
    {
        int total = SC_M * 128 + 2 * GH_M * 128 + 128 * 128;
        prep_weights<<<(total + 255) / 256, 256>>>(W1, b1, Wih, Whh, Wout);
    }
    cudaEventRecord(evSp, s1);
    cudaStreamWaitEvent(0, evSp, 0);

    // proj (needs prep + split)
    proj_all<<<dim3(5, NBLK), 256, PIPE_SMEM>>>(node_attr, bih, NN);

    // fork: walk3 on s1 || (gru0 -> GEMM1) on 0
    cudaEventRecord(evP, 0);
    cudaStreamWaitEvent(s1, evP, 0);
    walk3<<<WALK_BLKS, 256, 0, s1>>>(dst, W2, b2, noise);
    gru0<<<GRU0_BLKS, 256>>>(bhh);
    mma_gemm_h<<<dim3(3, NBLK), 256, PIPE_SMEM>>>(pHAh, pHAl, pWhhH, pWhhL, bhh, pGH, NN, GH_M);
    cudaEventRecord(evW, s1);
    cudaStreamWaitEvent(0, evW, 0);

    // join: sequential GRU chain on 0
    gru_elem<<<EBLK, 256>>>(pHAh, pHAl, pHBh, pHBl, 1);
    mma_gemm_h<<<dim3(3, NBLK), 256, PIPE_SMEM>>>(pHBh, pHBl, pWhhH, pWhhL, bhh, pGH, NN, GH_M);
    gru_elem<<<EBLK, 256>>>(pHBh, pHBl, pHAh, pHAl, 2);
    mma_gemm_h<<<dim3(3, NBLK), 256, PIPE_SMEM>>>(pHAh, pHAl, pWhhH, pWhhL, bhh, pGH, NN, GH_M);
    gru_elem<<<EBLK, 256>>>(pHAh, pHAl, pHBh, pHBl, 3);
    mma_gemm_h<<<dim3(1, NBLK), 256, PIPE_SMEM>>>(pHBh, pHBl, pWoutH, pWoutL, bout, out, NN, HID);
}

// round 15
// speedup vs baseline: 1.2980x; 1.0508x over previous
#include <cuda_runtime.h>
#include <cuda_fp16.h>
#include <cstdint>
#include <math.h>

#define NN      20000
#define DEG     16
#define TT      3
#define HID     128
#define EPS_SEL 0.01f
#define SC_M    256
#define GH_M    384
#define NBLK    313            // ceil(20000/64)
#define HALF_N  10000
#define NBLK_H  157            // ceil(10000/64)

// ---------------- device scratch ----------------
__device__ float g_SC [(size_t)NN * SC_M];
__device__ float g_G  [(size_t)NN * GH_M];
__device__ float g_GH [(size_t)NN * GH_M];
__device__ __align__(16) __half g_vh [(size_t)NN * 128];
__device__ __align__(16) __half g_vl [(size_t)NN * 128];
__device__ __align__(16) __half g_hAh[(size_t)NN * HID];
__device__ __align__(16) __half g_hAl[(size_t)NN * HID];
__device__ __align__(16) __half g_hBh[(size_t)NN * HID];
__device__ __align__(16) __half g_hBl[(size_t)NN * HID];
__device__ int   g_sel[TT * NN];
__device__ float g_Bsc_t[SC_M * 128];
__device__ float g_bias_sc[SC_M];
__device__ __align__(16) __half g_Wih_h[GH_M * 128], g_Wih_l[GH_M * 128];
__device__ __align__(16) __half g_Whh_h[GH_M * 128], g_Whh_l[GH_M * 128];
__device__ __align__(16) __half g_Wout_h[128 * 128], g_Wout_l[128 * 128];

__device__ __forceinline__ uint32_t smem_u32(const void* p) {
    uint32_t a;
    asm("{ .reg .u64 t; cvta.to.shared.u64 t, %1; cvt.u32.u64 %0, t; }" : "=r"(a) : "l"(p));
    return a;
}
__device__ __forceinline__ uint32_t f2tf32(float x) {
    uint32_t r;
    asm("cvt.rna.tf32.f32 %0, %1;" : "=r"(r) : "f"(x));
    return r;
}
#define CP16(dst, src) \
    asm volatile("cp.async.cg.shared.global [%0], [%1], 16;" :: "r"(dst), "l"(src))
#define CP_COMMIT() asm volatile("cp.async.commit_group;" ::: "memory")
#define CP_WAIT(n)  asm volatile("cp.async.wait_group %0;" :: "n"(n) : "memory")

// ---------------- merged weight prep + node_attr split ----------------
#define PREP_TOTAL (SC_M * 128 + 2 * GH_M * 128 + 128 * 128)   // 147456
#define SPLIT_TOTAL (NN * 128 / 4)                              // 640000
__global__ void prep_split(const float* __restrict__ W1, const float* __restrict__ b1,
                           const float* __restrict__ Wih, const float* __restrict__ Whh,
                           const float* __restrict__ Wout, const float* __restrict__ A) {
    int i = blockIdx.x * blockDim.x + threadIdx.x;
    if (i < PREP_TOTAL) {
        if (i < SC_M * 128) {
            int j = i / 128, k = i % 128;
            int s = j >> 6, m = j & 63;
            g_Bsc_t[i] = W1[(size_t)(s * 128 + k) * 64 + m];
            if (k == 0) g_bias_sc[j] = (j < 64) ? b1[j] : 0.0f;
            return;
        }
        int i2 = i - SC_M * 128;
        float w;
        __half *dh, *dl;
        if (i2 < GH_M * 128) { w = Wih[i2]; dh = g_Wih_h; dl = g_Wih_l; }
        else if (i2 < 2 * GH_M * 128) { i2 -= GH_M * 128; w = Whh[i2]; dh = g_Whh_h; dl = g_Whh_l; }
        else {
            i2 -= 2 * GH_M * 128;
            int n = i2 / 128, k = i2 % 128;
            w = Wout[(size_t)k * 128 + n];
            dh = g_Wout_h; dl = g_Wout_l;
        }
        __half hi = __float2half_rn(w);
        dh[i2] = hi;
        dl[i2] = __float2half_rn(w - __half2float(hi));
        return;
    }
    int t = i - PREP_TOTAL;
    if (t >= SPLIT_TOTAL) return;
    int e = t * 4;
    float4 a = *(const float4*)(A + e);
    float av[4] = {a.x, a.y, a.z, a.w};
    __half hv[4], lv[4];
#pragma unroll
    for (int q = 0; q < 4; q++) {
        hv[q] = __float2half_rn(av[q]);
        lv[q] = __float2half_rn(av[q] - __half2float(hv[q]));
    }
    *(uint2*)(g_vh + e) = *(uint2*)hv;
    *(uint2*)(g_vl + e) = *(uint2*)lv;
}

// ================= pipelined GEMM constants (2 x 64-k chunks, 2 stages) =================
#define HLDS 72
#define SA_H 0
#define SA_L (64 * HLDS * 2)
#define SB_H (2 * 64 * HLDS * 2)
#define SB_L (SB_H + 128 * HLDS * 2)
#define STAGE_BYTES (SB_L + 128 * HLDS * 2)      // 55296
#define PIPE_SMEM (2 * STAGE_BYTES)              // 110592

// pipelined fp16x2-split 64x128 GEMM tile body — 256 threads, 8 warps (2x4), warp tile 32x32
__device__ __forceinline__ void pipe_gemm_body(const __half* __restrict__ Ah,
                                               const __half* __restrict__ Al,
                                               const __half* __restrict__ bh,
                                               const __half* __restrict__ bl,
                                               const float* __restrict__ bias,
                                               float* __restrict__ C, int rows, int ldc,
                                               int rowBase, int colBase,
                                               char* smem) {
    uint32_t sb = smem_u32(smem);
    int tid = threadIdx.x;
    int lane = tid & 31;
    int wid = tid >> 5;
    int wm = wid >> 2, wn = wid & 3;   // 2 x 4 warps

#pragma unroll
    for (int kc = 0; kc < 2; kc++) {
        uint32_t stage = sb + kc * STAGE_BYTES;
        int kof = kc * 64;
#pragma unroll
        for (int i = 0; i < 2; i++) {
            int idx = tid + 256 * i;
            int r = idx >> 3, j = (idx & 7) * 8;
            int gr = rowBase + r;
            if (gr >= rows) gr = rows - 1;
            uint32_t off = (uint32_t)((r * HLDS + j) * 2);
            CP16(stage + SA_H + off, Ah + (size_t)gr * 128 + kof + j);
            CP16(stage + SA_L + off, Al + (size_t)gr * 128 + kof + j);
        }
#pragma unroll
        for (int i = 0; i < 4; i++) {
            int idx = tid + 256 * i;
            int r = idx >> 3, j = (idx & 7) * 8;
            uint32_t off = (uint32_t)((r * HLDS + j) * 2);
            CP16(stage + SB_H + off, bh + (size_t)r * 128 + kof + j);
            CP16(stage + SB_L + off, bl + (size_t)r * 128 + kof + j);
        }
        CP_COMMIT();
    }

    float acc[2][4][4];
#pragma unroll
    for (int mi = 0; mi < 2; mi++)
#pragma unroll
        for (int ni = 0; ni < 4; ni++)
#pragma unroll
            for (int q = 0; q < 4; q++) acc[mi][ni][q] = 0.0f;

    int a_r = lane & 15, a_c = (lane >> 4) * 8;
    int b_r = (lane & 7) + ((lane >> 4) << 3), b_c = ((lane >> 3) & 1) * 8;

#pragma unroll
    for (int kc = 0; kc < 2; kc++) {
        if (kc == 0) { CP_WAIT(1); } else { CP_WAIT(0); }
        __syncthreads();
        uint32_t stage = sb + kc * STAGE_BYTES;
        const uint32_t aOffT[3] = {stage + SA_H, stage + SA_H, stage + SA_L};
        const uint32_t bOffT[3] = {stage + SB_H, stage + SB_L, stage + SB_H};
#pragma unroll
        for (int term = 0; term < 3; term++) {
            uint32_t abase = aOffT[term], bbase = bOffT[term];
#pragma unroll
            for (int k0 = 0; k0 < 4; k0++) {
                int kk = k0 * 16;
                uint32_t af[2][4];
#pragma unroll
                for (int mi = 0; mi < 2; mi++) {
                    uint32_t addr = abase +
                        (uint32_t)(((wm * 32 + mi * 16 + a_r) * HLDS + kk + a_c) * 2);
                    asm volatile("ldmatrix.sync.aligned.m8n8.x4.shared.b16 {%0,%1,%2,%3}, [%4];"
                                 : "=r"(af[mi][0]), "=r"(af[mi][1]),
                                   "=r"(af[mi][2]), "=r"(af[mi][3]) : "r"(addr));
                }
                uint32_t bf[4][2];
#pragma unroll
                for (int nj = 0; nj < 2; nj++) {
                    uint32_t ba = bbase +
                        (uint32_t)(((wn * 32 + nj * 16 + b_r) * HLDS + kk + b_c) * 2);
                    uint32_t r0, r1, r2, r3;
                    asm volatile("ldmatrix.sync.aligned.m8n8.x4.shared.b16 {%0,%1,%2,%3}, [%4];"
                                 : "=r"(r0), "=r"(r1), "=r"(r2), "=r"(r3) : "r"(ba));
                    bf[2 * nj][0] = r0; bf[2 * nj][1] = r1;
                    bf[2 * nj + 1][0] = r2; bf[2 * nj + 1][1] = r3;
                }
#pragma unroll
                for (int mi = 0; mi < 2; mi++)
#pragma unroll
                    for (int ni = 0; ni < 4; ni++)
                        asm volatile(
                            "mma.sync.aligned.m16n8k16.row.col.f32.f16.f16.f32 "
                            "{%0,%1,%2,%3}, {%4,%5,%6,%7}, {%8,%9}, {%0,%1,%2,%3};"
                            : "+f"(acc[mi][ni][0]), "+f"(acc[mi][ni][1]),
                              "+f"(acc[mi][ni][2]), "+f"(acc[mi][ni][3])
                            : "r"(af[mi][0]), "r"(af[mi][1]), "r"(af[mi][2]), "r"(af[mi][3]),
                              "r"(bf[ni][0]), "r"(bf[ni][1]));
            }
        }
    }

    int cb = colBase + wn * 32;
#pragma unroll
    for (int mi = 0; mi < 2; mi++) {
        int rb = rowBase + wm * 32 + mi * 16;
#pragma unroll
        for (int ni = 0; ni < 4; ni++) {
            int r0 = rb + (lane >> 2);
            int c0 = cb + ni * 8 + (lane & 3) * 2;
            float bv0 = bias[c0], bv1 = bias[c0 + 1];
            if (r0 < rows)
                *(float2*)(C + (size_t)r0 * ldc + c0) =
                    make_float2(acc[mi][ni][0] + bv0, acc[mi][ni][1] + bv1);
            if (r0 + 8 < rows)
                *(float2*)(C + (size_t)(r0 + 8) * ldc + c0) =
                    make_float2(acc[mi][ni][2] + bv0, acc[mi][ni][3] + bv1);
        }
    }
}

// ================= fused projection kernel (unchanged) =================
#define SLDS 132
__global__ __launch_bounds__(256, 2) void proj_all(const float* __restrict__ A,
                                                   const float* __restrict__ bih, int rows) {
    extern __shared__ __align__(16) char smem[];
    int tid = threadIdx.x;
    int lane = tid & 31;
    int wid = tid >> 5;
    int rowBase = blockIdx.y * 64;

    if (blockIdx.x >= 2) {
        int bx = blockIdx.x - 2;
        pipe_gemm_body(g_vh, g_vl,
                       g_Wih_h + (size_t)bx * 128 * 128, g_Wih_l + (size_t)bx * 128 * 128,
                       bih, g_G, rows, GH_M, rowBase, bx * 128, smem);
        return;
    }

    // ---------- tf32 scoring path (selection-critical, unchanged) ----------
    float* As = (float*)smem;
    float* Bs = As + 64 * SLDS;
    int colBase = blockIdx.x * 128;
    for (int c = tid; c < 2048; c += 256) {
        int r = c >> 5, k = (c & 31) * 4;
        int gr = rowBase + r;
        float4 a = make_float4(0.f, 0.f, 0.f, 0.f);
        if (gr < rows) a = *(const float4*)(A + (size_t)gr * 128 + k);
        *(float4*)(As + r * SLDS + k) = a;
    }
    for (int c = tid; c < 4096; c += 256) {
        int r = c >> 5, k = (c & 31) * 4;
        *(float4*)(Bs + r * SLDS + k) =
            *(const float4*)(g_Bsc_t + (size_t)(colBase + r) * 128 + k);
    }
    __syncthreads();

    int wm = wid >> 1, wn = wid & 1;
    int m0 = wm * 16, n0 = wn * 64;
    int gid = lane >> 2, tig = lane & 3;
    float acc[8][4];
#pragma unroll
    for (int ni = 0; ni < 8; ni++)
#pragma unroll
        for (int q = 0; q < 4; q++) acc[ni][q] = 0.0f;

#pragma unroll
    for (int k0 = 0; k0 < 16; k0++) {
        int kk = k0 * 8;
        float av[4] = {As[(m0 + gid) * SLDS + kk + tig],
                       As[(m0 + gid + 8) * SLDS + kk + tig],
                       As[(m0 + gid) * SLDS + kk + tig + 4],
                       As[(m0 + gid + 8) * SLDS + kk + tig + 4]};
        uint32_t ah[4], al[4];
#pragma unroll
        for (int q = 0; q < 4; q++) {
            ah[q] = f2tf32(av[q]);
            al[q] = f2tf32(av[q] - __uint_as_float(ah[q]));
        }
#pragma unroll
        for (int nf = 0; nf < 8; nf++) {
            float b0 = Bs[(n0 + nf * 8 + gid) * SLDS + kk + tig];
            float b1 = Bs[(n0 + nf * 8 + gid) * SLDS + kk + tig + 4];
            uint32_t bh0 = f2tf32(b0), bh1 = f2tf32(b1);
            uint32_t bl0 = f2tf32(b0 - __uint_as_float(bh0));
            uint32_t bl1 = f2tf32(b1 - __uint_as_float(bh1));
            asm volatile(
                "mma.sync.aligned.m16n8k8.row.col.f32.tf32.tf32.f32 "
                "{%0,%1,%2,%3}, {%4,%5,%6,%7}, {%8,%9}, {%0,%1,%2,%3};"
                : "+f"(acc[nf][0]), "+f"(acc[nf][1]), "+f"(acc[nf][2]), "+f"(acc[nf][3])
                : "r"(ah[0]), "r"(ah[1]), "r"(ah[2]), "r"(ah[3]), "r"(bh0), "r"(bh1));
            asm volatile(
                "mma.sync.aligned.m16n8k8.row.col.f32.tf32.tf32.f32 "
                "{%0,%1,%2,%3}, {%4,%5,%6,%7}, {%8,%9}, {%0,%1,%2,%3};"
                : "+f"(acc[nf][0]), "+f"(acc[nf][1]), "+f"(acc[nf][2]), "+f"(acc[nf][3])
                : "r"(ah[0]), "r"(ah[1]), "r"(ah[2]), "r"(ah[3]), "r"(bl0), "r"(bl1));
            asm volatile(
                "mma.sync.aligned.m16n8k8.row.col.f32.tf32.tf32.f32 "
                "{%0,%1,%2,%3}, {%4,%5,%6,%7}, {%8,%9}, {%0,%1,%2,%3};"
                : "+f"(acc[nf][0]), "+f"(acc[nf][1]), "+f"(acc[nf][2]), "+f"(acc[nf][3])
                : "r"(al[0]), "r"(al[1]), "r"(al[2]), "r"(al[3]), "r"(bh0), "r"(bh1));
        }
    }
    int rb = rowBase + m0;
#pragma unroll
    for (int nf = 0; nf < 8; nf++) {
        int c0 = colBase + n0 + nf * 8 + tig * 2;
        float bv0 = g_bias_sc[c0], bv1 = g_bias_sc[c0 + 1];
#pragma unroll
        for (int half = 0; half < 2; half++) {
            int r0 = rb + gid + half * 8;
            if (r0 >= rows) continue;
            *(float2*)(g_SC + (size_t)r0 * SC_M + c0) =
                make_float2(acc[nf][2 * half] + bv0, acc[nf][2 * half + 1] + bv1);
        }
    }
}

// ================= walk (3 steps) — unchanged =================
#define WALK_BLKS ((NN * 32 + 255) / 256)
__global__ __launch_bounds__(256) void walk3(const int* __restrict__ dst,
                                             const float* __restrict__ W2,
                                             const float* __restrict__ b2p,
                                             const float* __restrict__ noise) {
    const unsigned FULL = 0xFFFFFFFFu;
    int tid = threadIdx.x;
    int gwarp = (blockIdx.x * 256 + tid) >> 5;
    int lane = tid & 31;
    int wz = tid >> 5;
    __shared__ float s_logp[8][16];
    if (gwarp >= NN) return;
    int n = gwarp;
    int q = lane & 15;
    int h = lane >> 4;

    float4 bse = *(const float4*)(g_SC + (size_t)n * SC_M + q * 4);
    float4 w2 = *(const float4*)(W2 + q * 4);
    float b2 = b2p[0];
    int cur = n;

#pragma unroll
    for (int t = 0; t < TT; t++) {
        const int* nb = dst + (size_t)cur * DEG;
        const int slot = (1 + t) * 64;
#pragma unroll
        for (int it = 0; it < 8; it++) {
            int d = it * 2 + h;
            int cand = nb[d];
            float4 c = *(const float4*)(g_SC + (size_t)cand * SC_M + slot + q * 4);
            float s = fmaxf(bse.x + c.x, 0.f) * w2.x + fmaxf(bse.y + c.y, 0.f) * w2.y +
                      fmaxf(bse.z + c.z, 0.f) * w2.z + fmaxf(bse.w + c.w, 0.f) * w2.w;
#pragma unroll
            for (int off = 8; off >= 1; off >>= 1)
                s += __shfl_xor_sync(FULL, s, off);
            if (q == 0) s_logp[wz][d] = s + b2;
        }
        __syncwarp();
        float lp = (lane < DEG) ? s_logp[wz][lane] : -1e38f;
        float m = lp;
#pragma unroll
        for (int off = 8; off >= 1; off >>= 1)
            m = fmaxf(m, __shfl_xor_sync(FULL, m, off));
        float e = (lane < DEG) ? expf(lp - m) : 0.0f;
        float ssum = e;
#pragma unroll
        for (int off = 8; off >= 1; off >>= 1)
            ssum += __shfl_xor_sync(FULL, ssum, off);
        float norm = m + logf(ssum);
        float p = (lane < DEG)
                      ? expf(lp - norm) + EPS_SEL * noise[((size_t)t * NN + n) * DEG + lane]
                      : -1e38f;
        float bv = p;
        int bi = lane;
#pragma unroll
        for (int off = 8; off >= 1; off >>= 1) {
            float ov = __shfl_xor_sync(FULL, bv, off);
            int oi = __shfl_xor_sync(FULL, bi, off);
            if (ov > bv || (ov == bv && oi < bi)) { bv = ov; bi = oi; }
        }
        int bsel = __shfl_sync(FULL, bi, 0);
        int csel = nb[bsel];
        float4 c = *(const float4*)(g_SC + (size_t)csel * SC_M + slot + q * 4);
        bse.x += c.x; bse.y += c.y; bse.z += c.z; bse.w += c.w;
        cur = csel;
        if (lane == 0) g_sel[t * NN + n] = csel;
        __syncwarp();
    }
}

// ================= gru0 (h_prev = 0) — unchanged =================
#define GRU0_BLKS ((NN * 32 + 255) / 256)
__global__ __launch_bounds__(256) void gru0(const float* __restrict__ bhh) {
    int gt = blockIdx.x * 256 + threadIdx.x;
    int n = gt >> 5, c4 = (gt & 31) * 4;
    if (n >= NN) return;
    const float* gi = g_G + (size_t)n * GH_M;
    float4 gir = *(const float4*)(gi + c4);
    float4 giz = *(const float4*)(gi + 128 + c4);
    float4 gin = *(const float4*)(gi + 256 + c4);
    float4 br = *(const float4*)(bhh + c4);
    float4 bz = *(const float4*)(bhh + 128 + c4);
    float4 bn = *(const float4*)(bhh + 256 + c4);
    float o[4];
    {
        float r = 1.0f / (1.0f + expf(-(gir.x + br.x)));
        float z = 1.0f / (1.0f + expf(-(giz.x + bz.x)));
        o[0] = (1.0f - z) * tanhf(gin.x + r * bn.x);
    }
    {
        float r = 1.0f / (1.0f + expf(-(gir.y + br.y)));
        float z = 1.0f / (1.0f + expf(-(giz.y + bz.y)));
        o[1] = (1.0f - z) * tanhf(gin.y + r * bn.y);
    }
    {
        float r = 1.0f / (1.0f + expf(-(gir.z + br.z)));
        float z = 1.0f / (1.0f + expf(-(giz.z + bz.z)));
        o[2] = (1.0f - z) * tanhf(gin.z + r * bn.z);
    }
    {
        float r = 1.0f / (1.0f + expf(-(gir.w + br.w)));
        float z = 1.0f / (1.0f + expf(-(giz.w + bz.w)));
        o[3] = (1.0f - z) * tanhf(gin.w + r * bn.w);
    }
    __half hv[4], lv[4];
#pragma unroll
    for (int q = 0; q < 4; q++) {
        hv[q] = __float2half_rn(o[q]);
        lv[q] = __float2half_rn(o[q] - __half2float(hv[q]));
    }
    *(uint2*)(g_hAh + (size_t)n * HID + c4) = *(uint2*)hv;
    *(uint2*)(g_hAl + (size_t)n * HID + c4) = *(uint2*)lv;
}

// ================= pipelined GEMM kernel with row offset =================
__global__ __launch_bounds__(256, 2) void mma_gemm_h(const __half* __restrict__ Ah,
                                                     const __half* __restrict__ Al,
                                                     const __half* __restrict__ Bh,
                                                     const __half* __restrict__ Bl,
                                                     const float* __restrict__ bias,
                                                     float* __restrict__ C,
                                                     int rowOff, int rowEnd, int ldc) {
    extern __shared__ __align__(16) char smem[];
    pipe_gemm_body(Ah, Al,
                   Bh + (size_t)blockIdx.x * 128 * 128, Bl + (size_t)blockIdx.x * 128 * 128,
                   bias, C, rowEnd, ldc, rowOff + blockIdx.y * 64, blockIdx.x * 128, smem);
}

// ================= GRU elementwise gates with row offset =================
__global__ __launch_bounds__(256) void gru_elem(const __half* __restrict__ hinh,
                                                const __half* __restrict__ hinl,
                                                __half* __restrict__ houth,
                                                __half* __restrict__ houtl,
                                                int step, int rowOff) {
    int gt = blockIdx.x * blockDim.x + threadIdx.x;
    int n = rowOff + (gt >> 5);
    int c4 = (gt & 31) * 4;
    int src = g_sel[(step - 1) * NN + n];
    const float* gi = g_G + (size_t)src * GH_M;
    const float* gh = g_GH + (size_t)n * GH_M;
    float4 gir = *(const float4*)(gi + c4);
    float4 giz = *(const float4*)(gi + 128 + c4);
    float4 gin = *(const float4*)(gi + 256 + c4);
    float4 ghr = *(const float4*)(gh + c4);
    float4 ghz = *(const float4*)(gh + 128 + c4);
    float4 ghn = *(const float4*)(gh + 256 + c4);
    uint2 hpu = *(const uint2*)(hinh + (size_t)n * HID + c4);
    uint2 hlu = *(const uint2*)(hinl + (size_t)n * HID + c4);
    __half* hph = (__half*)&hpu;
    __half* hpl = (__half*)&hlu;
    float o[4];
    float gir_a[4] = {gir.x, gir.y, gir.z, gir.w};
    float giz_a[4] = {giz.x, giz.y, giz.z, giz.w};
    float gin_a[4] = {gin.x, gin.y, gin.z, gin.w};
    float ghr_a[4] = {ghr.x, ghr.y, ghr.z, ghr.w};
    float ghz_a[4] = {ghz.x, ghz.y, ghz.z, ghz.w};
    float ghn_a[4] = {ghn.x, ghn.y, ghn.z, ghn.w};
#pragma unroll
    for (int q = 0; q < 4; q++) {
        float hp = __half2float(hph[q]) + __half2float(hpl[q]);
        float r = 1.0f / (1.0f + expf(-(gir_a[q] + ghr_a[q])));
        float z = 1.0f / (1.0f + expf(-(giz_a[q] + ghz_a[q])));
        o[q] = (1.0f - z) * tanhf(gin_a[q] + r * ghn_a[q]) + z * hp;
    }
    __half hv[4], lv[4];
#pragma unroll
    for (int q = 0; q < 4; q++) {
        hv[q] = __float2half_rn(o[q]);
        lv[q] = __float2half_rn(o[q] - __half2float(hv[q]));
    }
    *(uint2*)(houth + (size_t)n * HID + c4) = *(uint2*)hv;
    *(uint2*)(houtl + (size_t)n * HID + c4) = *(uint2*)lv;
}

// ---------------- host launch ----------------
extern "C" void kernel_launch(void* const* d_in, const int* in_sizes, int n_in,
                              void* d_out, int out_size) {
    const float* node_attr = (const float*)d_in[0];
    const int*   edge_idx  = (const int*)d_in[1];
    const float* W1   = (const float*)d_in[3];
    const float* b1   = (const float*)d_in[4];
    const float* W2   = (const float*)d_in[5];
    const float* b2   = (const float*)d_in[6];
    const float* Wih  = (const float*)d_in[7];
    const float* Whh  = (const float*)d_in[8];
    const float* bih  = (const float*)d_in[9];
    const float* bhh  = (const float*)d_in[10];
    const float* Wout = (const float*)d_in[11];
    const float* bout = (const float*)d_in[12];
    const float* noise = (const float*)d_in[13];
    float* out = (float*)d_out;
    const int* dst = edge_idx + (size_t)NN * DEG;

    float *pGH;
    __half *pHAh, *pHAl, *pHBh, *pHBl, *pWhhH, *pWhhL, *pWoutH, *pWoutL;
    cudaGetSymbolAddress((void**)&pGH, g_GH);
    cudaGetSymbolAddress((void**)&pHAh, g_hAh);
    cudaGetSymbolAddress((void**)&pHAl, g_hAl);
    cudaGetSymbolAddress((void**)&pHBh, g_hBh);
    cudaGetSymbolAddress((void**)&pHBl, g_hBl);
    cudaGetSymbolAddress((void**)&pWhhH, g_Whh_h);
    cudaGetSymbolAddress((void**)&pWhhL, g_Whh_l);
    cudaGetSymbolAddress((void**)&pWoutH, g_Wout_h);
    cudaGetSymbolAddress((void**)&pWoutL, g_Wout_l);

    static bool init_done = false;
    static cudaStream_t s1;
    static cudaEvent_t evP, evW, evG1, evEnd;
    if (!init_done) {
        cudaFuncSetAttribute(proj_all, cudaFuncAttributeMaxDynamicSharedMemorySize, PIPE_SMEM);
        cudaFuncSetAttribute(mma_gemm_h, cudaFuncAttributeMaxDynamicSharedMemorySize, PIPE_SMEM);
        cudaStreamCreateWithFlags(&s1, cudaStreamNonBlocking);
        cudaEventCreateWithFlags(&evP, cudaEventDisableTiming);
        cudaEventCreateWithFlags(&evW, cudaEventDisableTiming);
        cudaEventCreateWithFlags(&evG1, cudaEventDisableTiming);
        cudaEventCreateWithFlags(&evEnd, cudaEventDisableTiming);
        init_done = true;
    }

    const int EBLK_H = HALF_N * 32 / 256;   // 1250

    // 1. merged weight prep + node_attr split (one kernel)
    prep_split<<<(PREP_TOTAL + SPLIT_TOTAL + 255) / 256, 256>>>(W1, b1, Wih, Whh, Wout,
                                                                node_attr);
    // 2. fused projections: g_SC (tf32) + g_G (pipelined fp16-split)
    proj_all<<<dim3(5, NBLK), 256, PIPE_SMEM>>>(node_attr, bih, NN);

    // 3. fork: walk3 on s1 || (gru0 -> full GEMM1) on 0
    cudaEventRecord(evP, 0);
    cudaStreamWaitEvent(s1, evP, 0);
    walk3<<<WALK_BLKS, 256, 0, s1>>>(dst, W2, b2, noise);
    gru0<<<GRU0_BLKS, 256>>>(bhh);
    mma_gemm_h<<<dim3(3, NBLK), 256, PIPE_SMEM>>>(pHAh, pHAl, pWhhH, pWhhL, bhh, pGH,
                                                  0, NN, GH_M);
    cudaEventRecord(evW, s1);
    cudaStreamWaitEvent(0, evW, 0);
    cudaEventRecord(evG1, 0);         // walk3 + GEMM1 both complete
    cudaStreamWaitEvent(s1, evG1, 0);

    // 4. row-split GRU chains: half-1 on stream 0, half-2 on s1
    // half-1 (rows [0, 10000))
    gru_elem<<<EBLK_H, 256>>>(pHAh, pHAl, pHBh, pHBl, 1, 0);
    mma_gemm_h<<<dim3(3, NBLK_H), 256, PIPE_SMEM>>>(pHBh, pHBl, pWhhH, pWhhL, bhh, pGH,
                                                    0, HALF_N, GH_M);
    gru_elem<<<EBLK_H, 256>>>(pHBh, pHBl, pHAh, pHAl, 2, 0);
    mma_gemm_h<<<dim3(3, NBLK_H), 256, PIPE_SMEM>>>(pHAh, pHAl, pWhhH, pWhhL, bhh, pGH,
                                                    0, HALF_N, GH_M);
    gru_elem<<<EBLK_H, 256>>>(pHAh, pHAl, pHBh, pHBl, 3, 0);
    mma_gemm_h<<<dim3(1, NBLK_H), 256, PIPE_SMEM>>>(pHBh, pHBl, pWoutH, pWoutL, bout, out,
                                                    0, HALF_N, HID);
    // half-2 (rows [10000, 20000)) on s1
    gru_elem<<<EBLK_H, 256, 0, s1>>>(pHAh, pHAl, pHBh, pHBl, 1, HALF_N);
    mma_gemm_h<<<dim3(3, NBLK_H), 256, PIPE_SMEM, s1>>>(pHBh, pHBl, pWhhH, pWhhL, bhh, pGH,
                                                        HALF_N, NN, GH_M);
    gru_elem<<<EBLK_H, 256, 0, s1>>>(pHBh, pHBl, pHAh, pHAl, 2, HALF_N);
    mma_gemm_h<<<dim3(3, NBLK_H), 256, PIPE_SMEM, s1>>>(pHAh, pHAl, pWhhH, pWhhL, bhh, pGH,
                                                        HALF_N, NN, GH_M);
    gru_elem<<<EBLK_H, 256, 0, s1>>>(pHAh, pHAl, pHBh, pHBl, 3, HALF_N);
    mma_gemm_h<<<dim3(1, NBLK_H), 256, PIPE_SMEM, s1>>>(pHBh, pHBl, pWoutH, pWoutL, bout, out,
                                                        HALF_N, NN, HID);
    cudaEventRecord(evEnd, s1);
    cudaStreamWaitEvent(0, evEnd, 0);
}

// round 16
// speedup vs baseline: 1.3507x; 1.0406x over previous
#include <cuda_runtime.h>
#include <cuda_fp16.h>
#include <cstdint>
#include <math.h>

#define NN      20000
#define DEG     16
#define TT      3
#define HID     128
#define EPS_SEL 0.01f
#define SC_M    256
#define GH_M    384
#define NBLK    313            // ceil(20000/64)
#define HALF_N  10000
#define NBLK_H  157            // ceil(10000/64)

// ---------------- device scratch ----------------
__device__ float g_SC [(size_t)NN * SC_M];
__device__ float g_G  [(size_t)NN * GH_M];
__device__ float g_GH [(size_t)NN * GH_M];
__device__ __align__(16) __half g_vh [(size_t)NN * 128];
__device__ __align__(16) __half g_vl [(size_t)NN * 128];
__device__ __align__(16) __half g_hAh[(size_t)NN * HID];
__device__ __align__(16) __half g_hAl[(size_t)NN * HID];
__device__ __align__(16) __half g_hBh[(size_t)NN * HID];
__device__ __align__(16) __half g_hBl[(size_t)NN * HID];
__device__ int   g_sel[TT * NN];
__device__ float g_Bsc_t[SC_M * 128];
__device__ float g_bias_sc[SC_M];
__device__ __align__(16) __half g_Wih_h[GH_M * 128], g_Wih_l[GH_M * 128];
__device__ __align__(16) __half g_Whh_h[GH_M * 128], g_Whh_l[GH_M * 128];
__device__ __align__(16) __half g_Wout_h[128 * 128], g_Wout_l[128 * 128];

__device__ __forceinline__ uint32_t smem_u32(const void* p) {
    uint32_t a;
    asm("{ .reg .u64 t; cvta.to.shared.u64 t, %1; cvt.u32.u64 %0, t; }" : "=r"(a) : "l"(p));
    return a;
}
__device__ __forceinline__ uint32_t f2tf32(float x) {
    uint32_t r;
    asm("cvt.rna.tf32.f32 %0, %1;" : "=r"(r) : "f"(x));
    return r;
}
#define CP16(dst, src) \
    asm volatile("cp.async.cg.shared.global [%0], [%1], 16;" :: "r"(dst), "l"(src))
#define CP_COMMIT() asm volatile("cp.async.commit_group;" ::: "memory")
#define CP_WAIT(n)  asm volatile("cp.async.wait_group %0;" :: "n"(n) : "memory")

// ---------------- merged weight prep + node_attr split ----------------
#define PREP_TOTAL (SC_M * 128 + 2 * GH_M * 128 + 128 * 128)   // 147456
#define SPLIT_TOTAL (NN * 128 / 4)                              // 640000
__global__ void prep_split(const float* __restrict__ W1, const float* __restrict__ b1,
                           const float* __restrict__ Wih, const float* __restrict__ Whh,
                           const float* __restrict__ Wout, const float* __restrict__ A) {
    int i = blockIdx.x * blockDim.x + threadIdx.x;
    if (i < PREP_TOTAL) {
        if (i < SC_M * 128) {
            int j = i / 128, k = i % 128;
            int s = j >> 6, m = j & 63;
            g_Bsc_t[i] = W1[(size_t)(s * 128 + k) * 64 + m];
            if (k == 0) g_bias_sc[j] = (j < 64) ? b1[j] : 0.0f;
            return;
        }
        int i2 = i - SC_M * 128;
        float w;
        __half *dh, *dl;
        if (i2 < GH_M * 128) { w = Wih[i2]; dh = g_Wih_h; dl = g_Wih_l; }
        else if (i2 < 2 * GH_M * 128) { i2 -= GH_M * 128; w = Whh[i2]; dh = g_Whh_h; dl = g_Whh_l; }
        else {
            i2 -= 2 * GH_M * 128;
            int n = i2 / 128, k = i2 % 128;
            w = Wout[(size_t)k * 128 + n];
            dh = g_Wout_h; dl = g_Wout_l;
        }
        __half hi = __float2half_rn(w);
        dh[i2] = hi;
        dl[i2] = __float2half_rn(w - __half2float(hi));
        return;
    }
    int t = i - PREP_TOTAL;
    if (t >= SPLIT_TOTAL) return;
    int e = t * 4;
    float4 a = *(const float4*)(A + e);
    float av[4] = {a.x, a.y, a.z, a.w};
    __half hv[4], lv[4];
#pragma unroll
    for (int q = 0; q < 4; q++) {
        hv[q] = __float2half_rn(av[q]);
        lv[q] = __float2half_rn(av[q] - __half2float(hv[q]));
    }
    *(uint2*)(g_vh + e) = *(uint2*)hv;
    *(uint2*)(g_vl + e) = *(uint2*)lv;
}

// ================= pipelined GEMM constants (2 x 64-k chunks, 2 stages) =================
#define HLDS 72
#define SA_H 0
#define SA_L (64 * HLDS * 2)
#define SB_H (2 * 64 * HLDS * 2)
#define SB_L (SB_H + 128 * HLDS * 2)
#define STAGE_BYTES (SB_L + 128 * HLDS * 2)      // 55296
#define PIPE_SMEM (2 * STAGE_BYTES)              // 110592

// pipelined fp16x2-split 64x128 GEMM tile body — 256 threads, 8 warps (2x4), warp tile 32x32
__device__ __forceinline__ void pipe_gemm_body(const __half* __restrict__ Ah,
                                               const __half* __restrict__ Al,
                                               const __half* __restrict__ bh,
                                               const __half* __restrict__ bl,
                                               const float* __restrict__ bias,
                                               float* __restrict__ C, int rows, int ldc,
                                               int rowBase, int colBase,
                                               char* smem) {
    uint32_t sb = smem_u32(smem);
    int tid = threadIdx.x;
    int lane = tid & 31;
    int wid = tid >> 5;
    int wm = wid >> 2, wn = wid & 3;   // 2 x 4 warps

#pragma unroll
    for (int kc = 0; kc < 2; kc++) {
        uint32_t stage = sb + kc * STAGE_BYTES;
        int kof = kc * 64;
#pragma unroll
        for (int i = 0; i < 2; i++) {
            int idx = tid + 256 * i;
            int r = idx >> 3, j = (idx & 7) * 8;
            int gr = rowBase + r;
            if (gr >= rows) gr = rows - 1;
            uint32_t off = (uint32_t)((r * HLDS + j) * 2);
            CP16(stage + SA_H + off, Ah + (size_t)gr * 128 + kof + j);
            CP16(stage + SA_L + off, Al + (size_t)gr * 128 + kof + j);
        }
#pragma unroll
        for (int i = 0; i < 4; i++) {
            int idx = tid + 256 * i;
            int r = idx >> 3, j = (idx & 7) * 8;
            uint32_t off = (uint32_t)((r * HLDS + j) * 2);
            CP16(stage + SB_H + off, bh + (size_t)r * 128 + kof + j);
            CP16(stage + SB_L + off, bl + (size_t)r * 128 + kof + j);
        }
        CP_COMMIT();
    }

    float acc[2][4][4];
#pragma unroll
    for (int mi = 0; mi < 2; mi++)
#pragma unroll
        for (int ni = 0; ni < 4; ni++)
#pragma unroll
            for (int q = 0; q < 4; q++) acc[mi][ni][q] = 0.0f;

    int a_r = lane & 15, a_c = (lane >> 4) * 8;
    int b_r = (lane & 7) + ((lane >> 4) << 3), b_c = ((lane >> 3) & 1) * 8;

#pragma unroll
    for (int kc = 0; kc < 2; kc++) {
        if (kc == 0) { CP_WAIT(1); } else { CP_WAIT(0); }
        __syncthreads();
        uint32_t stage = sb + kc * STAGE_BYTES;
        const uint32_t aOffT[3] = {stage + SA_H, stage + SA_H, stage + SA_L};
        const uint32_t bOffT[3] = {stage + SB_H, stage + SB_L, stage + SB_H};
#pragma unroll
        for (int term = 0; term < 3; term++) {
            uint32_t abase = aOffT[term], bbase = bOffT[term];
#pragma unroll
            for (int k0 = 0; k0 < 4; k0++) {
                int kk = k0 * 16;
                uint32_t af[2][4];
#pragma unroll
                for (int mi = 0; mi < 2; mi++) {
                    uint32_t addr = abase +
                        (uint32_t)(((wm * 32 + mi * 16 + a_r) * HLDS + kk + a_c) * 2);
                    asm volatile("ldmatrix.sync.aligned.m8n8.x4.shared.b16 {%0,%1,%2,%3}, [%4];"
                                 : "=r"(af[mi][0]), "=r"(af[mi][1]),
                                   "=r"(af[mi][2]), "=r"(af[mi][3]) : "r"(addr));
                }
                uint32_t bf[4][2];
#pragma unroll
                for (int nj = 0; nj < 2; nj++) {
                    uint32_t ba = bbase +
                        (uint32_t)(((wn * 32 + nj * 16 + b_r) * HLDS + kk + b_c) * 2);
                    uint32_t r0, r1, r2, r3;
                    asm volatile("ldmatrix.sync.aligned.m8n8.x4.shared.b16 {%0,%1,%2,%3}, [%4];"
                                 : "=r"(r0), "=r"(r1), "=r"(r2), "=r"(r3) : "r"(ba));
                    bf[2 * nj][0] = r0; bf[2 * nj][1] = r1;
                    bf[2 * nj + 1][0] = r2; bf[2 * nj + 1][1] = r3;
                }
#pragma unroll
                for (int mi = 0; mi < 2; mi++)
#pragma unroll
                    for (int ni = 0; ni < 4; ni++)
                        asm volatile(
                            "mma.sync.aligned.m16n8k16.row.col.f32.f16.f16.f32 "
                            "{%0,%1,%2,%3}, {%4,%5,%6,%7}, {%8,%9}, {%0,%1,%2,%3};"
                            : "+f"(acc[mi][ni][0]), "+f"(acc[mi][ni][1]),
                              "+f"(acc[mi][ni][2]), "+f"(acc[mi][ni][3])
                            : "r"(af[mi][0]), "r"(af[mi][1]), "r"(af[mi][2]), "r"(af[mi][3]),
                              "r"(bf[ni][0]), "r"(bf[ni][1]));
            }
        }
    }

    int cb = colBase + wn * 32;
#pragma unroll
    for (int mi = 0; mi < 2; mi++) {
        int rb = rowBase + wm * 32 + mi * 16;
#pragma unroll
        for (int ni = 0; ni < 4; ni++) {
            int r0 = rb + (lane >> 2);
            int c0 = cb + ni * 8 + (lane & 3) * 2;
            float bv0 = bias[c0], bv1 = bias[c0 + 1];
            if (r0 < rows)
                *(float2*)(C + (size_t)r0 * ldc + c0) =
                    make_float2(acc[mi][ni][0] + bv0, acc[mi][ni][1] + bv1);
            if (r0 + 8 < rows)
                *(float2*)(C + (size_t)(r0 + 8) * ldc + c0) =
                    make_float2(acc[mi][ni][2] + bv0, acc[mi][ni][3] + bv1);
        }
    }
}

// ================= Wih projection kernel (fp16 tiles of former proj_all) =================
__global__ __launch_bounds__(256, 2) void proj_wih(const float* __restrict__ bih, int rows) {
    extern __shared__ __align__(16) char smem[];
    int bx = blockIdx.x;
    pipe_gemm_body(g_vh, g_vl,
                   g_Wih_h + (size_t)bx * 128 * 128, g_Wih_l + (size_t)bx * 128 * 128,
                   bih, g_G, rows, GH_M, blockIdx.y * 64, bx * 128, smem);
}

// ================= scoring projection kernel (tf32 tiles of former proj_all) =================
#define SLDS 132
#define SCORE_SMEM ((64 + 128) * SLDS * 4)
__global__ __launch_bounds__(256, 2) void proj_score(const float* __restrict__ A, int rows) {
    extern __shared__ __align__(16) char smem[];
    int tid = threadIdx.x;
    int lane = tid & 31;
    int wid = tid >> 5;
    int rowBase = blockIdx.y * 64;

    float* As = (float*)smem;
    float* Bs = As + 64 * SLDS;
    int colBase = blockIdx.x * 128;
    for (int c = tid; c < 2048; c += 256) {
        int r = c >> 5, k = (c & 31) * 4;
        int gr = rowBase + r;
        float4 a = make_float4(0.f, 0.f, 0.f, 0.f);
        if (gr < rows) a = *(const float4*)(A + (size_t)gr * 128 + k);
        *(float4*)(As + r * SLDS + k) = a;
    }
    for (int c = tid; c < 4096; c += 256) {
        int r = c >> 5, k = (c & 31) * 4;
        *(float4*)(Bs + r * SLDS + k) =
            *(const float4*)(g_Bsc_t + (size_t)(colBase + r) * 128 + k);
    }
    __syncthreads();

    int wm = wid >> 1, wn = wid & 1;
    int m0 = wm * 16, n0 = wn * 64;
    int gid = lane >> 2, tig = lane & 3;
    float acc[8][4];
#pragma unroll
    for (int ni = 0; ni < 8; ni++)
#pragma unroll
        for (int q = 0; q < 4; q++) acc[ni][q] = 0.0f;

#pragma unroll
    for (int k0 = 0; k0 < 16; k0++) {
        int kk = k0 * 8;
        float av[4] = {As[(m0 + gid) * SLDS + kk + tig],
                       As[(m0 + gid + 8) * SLDS + kk + tig],
                       As[(m0 + gid) * SLDS + kk + tig + 4],
                       As[(m0 + gid + 8) * SLDS + kk + tig + 4]};
        uint32_t ah[4], al[4];
#pragma unroll
        for (int q = 0; q < 4; q++) {
            ah[q] = f2tf32(av[q]);
            al[q] = f2tf32(av[q] - __uint_as_float(ah[q]));
        }
#pragma unroll
        for (int nf = 0; nf < 8; nf++) {
            float b0 = Bs[(n0 + nf * 8 + gid) * SLDS + kk + tig];
            float b1 = Bs[(n0 + nf * 8 + gid) * SLDS + kk + tig + 4];
            uint32_t bh0 = f2tf32(b0), bh1 = f2tf32(b1);
            uint32_t bl0 = f2tf32(b0 - __uint_as_float(bh0));
            uint32_t bl1 = f2tf32(b1 - __uint_as_float(bh1));
            asm volatile(
                "mma.sync.aligned.m16n8k8.row.col.f32.tf32.tf32.f32 "
                "{%0,%1,%2,%3}, {%4,%5,%6,%7}, {%8,%9}, {%0,%1,%2,%3};"
                : "+f"(acc[nf][0]), "+f"(acc[nf][1]), "+f"(acc[nf][2]), "+f"(acc[nf][3])
                : "r"(ah[0]), "r"(ah[1]), "r"(ah[2]), "r"(ah[3]), "r"(bh0), "r"(bh1));
            asm volatile(
                "mma.sync.aligned.m16n8k8.row.col.f32.tf32.tf32.f32 "
                "{%0,%1,%2,%3}, {%4,%5,%6,%7}, {%8,%9}, {%0,%1,%2,%3};"
                : "+f"(acc[nf][0]), "+f"(acc[nf][1]), "+f"(acc[nf][2]), "+f"(acc[nf][3])
                : "r"(ah[0]), "r"(ah[1]), "r"(ah[2]), "r"(ah[3]), "r"(bl0), "r"(bl1));
            asm volatile(
                "mma.sync.aligned.m16n8k8.row.col.f32.tf32.tf32.f32 "
                "{%0,%1,%2,%3}, {%4,%5,%6,%7}, {%8,%9}, {%0,%1,%2,%3};"
                : "+f"(acc[nf][0]), "+f"(acc[nf][1]), "+f"(acc[nf][2]), "+f"(acc[nf][3])
                : "r"(al[0]), "r"(al[1]), "r"(al[2]), "r"(al[3]), "r"(bh0), "r"(bh1));
        }
    }
    int rb = rowBase + m0;
#pragma unroll
    for (int nf = 0; nf < 8; nf++) {
        int c0 = colBase + n0 + nf * 8 + tig * 2;
        float bv0 = g_bias_sc[c0], bv1 = g_bias_sc[c0 + 1];
#pragma unroll
        for (int half = 0; half < 2; half++) {
            int r0 = rb + gid + half * 8;
            if (r0 >= rows) continue;
            *(float2*)(g_SC + (size_t)r0 * SC_M + c0) =
                make_float2(acc[nf][2 * half] + bv0, acc[nf][2 * half + 1] + bv1);
        }
    }
}

// ================= walk (3 steps) — unchanged =================
#define WALK_BLKS ((NN * 32 + 255) / 256)
__global__ __launch_bounds__(256) void walk3(const int* __restrict__ dst,
                                             const float* __restrict__ W2,
                                             const float* __restrict__ b2p,
                                             const float* __restrict__ noise) {
    const unsigned FULL = 0xFFFFFFFFu;
    int tid = threadIdx.x;
    int gwarp = (blockIdx.x * 256 + tid) >> 5;
    int lane = tid & 31;
    int wz = tid >> 5;
    __shared__ float s_logp[8][16];
    if (gwarp >= NN) return;
    int n = gwarp;
    int q = lane & 15;
    int h = lane >> 4;

    float4 bse = *(const float4*)(g_SC + (size_t)n * SC_M + q * 4);
    float4 w2 = *(const float4*)(W2 + q * 4);
    float b2 = b2p[0];
    int cur = n;

#pragma unroll
    for (int t = 0; t < TT; t++) {
        const int* nb = dst + (size_t)cur * DEG;
        const int slot = (1 + t) * 64;
#pragma unroll
        for (int it = 0; it < 8; it++) {
            int d = it * 2 + h;
            int cand = nb[d];
            float4 c = *(const float4*)(g_SC + (size_t)cand * SC_M + slot + q * 4);
            float s = fmaxf(bse.x + c.x, 0.f) * w2.x + fmaxf(bse.y + c.y, 0.f) * w2.y +
                      fmaxf(bse.z + c.z, 0.f) * w2.z + fmaxf(bse.w + c.w, 0.f) * w2.w;
#pragma unroll
            for (int off = 8; off >= 1; off >>= 1)
                s += __shfl_xor_sync(FULL, s, off);
            if (q == 0) s_logp[wz][d] = s + b2;
        }
        __syncwarp();
        float lp = (lane < DEG) ? s_logp[wz][lane] : -1e38f;
        float m = lp;
#pragma unroll
        for (int off = 8; off >= 1; off >>= 1)
            m = fmaxf(m, __shfl_xor_sync(FULL, m, off));
        float e = (lane < DEG) ? expf(lp - m) : 0.0f;
        float ssum = e;
#pragma unroll
        for (int off = 8; off >= 1; off >>= 1)
            ssum += __shfl_xor_sync(FULL, ssum, off);
        float norm = m + logf(ssum);
        float p = (lane < DEG)
                      ? expf(lp - norm) + EPS_SEL * noise[((size_t)t * NN + n) * DEG + lane]
                      : -1e38f;
        float bv = p;
        int bi = lane;
#pragma unroll
        for (int off = 8; off >= 1; off >>= 1) {
            float ov = __shfl_xor_sync(FULL, bv, off);
            int oi = __shfl_xor_sync(FULL, bi, off);
            if (ov > bv || (ov == bv && oi < bi)) { bv = ov; bi = oi; }
        }
        int bsel = __shfl_sync(FULL, bi, 0);
        int csel = nb[bsel];
        float4 c = *(const float4*)(g_SC + (size_t)csel * SC_M + slot + q * 4);
        bse.x += c.x; bse.y += c.y; bse.z += c.z; bse.w += c.w;
        cur = csel;
        if (lane == 0) g_sel[t * NN + n] = csel;
        __syncwarp();
    }
}

// ================= gru0 (h_prev = 0) — unchanged =================
#define GRU0_BLKS ((NN * 32 + 255) / 256)
__global__ __launch_bounds__(256) void gru0(const float* __restrict__ bhh) {
    int gt = blockIdx.x * 256 + threadIdx.x;
    int n = gt >> 5, c4 = (gt & 31) * 4;
    if (n >= NN) return;
    const float* gi = g_G + (size_t)n * GH_M;
    float4 gir = *(const float4*)(gi + c4);
    float4 giz = *(const float4*)(gi + 128 + c4);
    float4 gin = *(const float4*)(gi + 256 + c4);
    float4 br = *(const float4*)(bhh + c4);
    float4 bz = *(const float4*)(bhh + 128 + c4);
    float4 bn = *(const float4*)(bhh + 256 + c4);
    float o[4];
    {
        float r = 1.0f / (1.0f + expf(-(gir.x + br.x)));
        float z = 1.0f / (1.0f + expf(-(giz.x + bz.x)));
        o[0] = (1.0f - z) * tanhf(gin.x + r * bn.x);
    }
    {
        float r = 1.0f / (1.0f + expf(-(gir.y + br.y)));
        float z = 1.0f / (1.0f + expf(-(giz.y + bz.y)));
        o[1] = (1.0f - z) * tanhf(gin.y + r * bn.y);
    }
    {
        float r = 1.0f / (1.0f + expf(-(gir.z + br.z)));
        float z = 1.0f / (1.0f + expf(-(giz.z + bz.z)));
        o[2] = (1.0f - z) * tanhf(gin.z + r * bn.z);
    }
    {
        float r = 1.0f / (1.0f + expf(-(gir.w + br.w)));
        float z = 1.0f / (1.0f + expf(-(giz.w + bz.w)));
        o[3] = (1.0f - z) * tanhf(gin.w + r * bn.w);
    }
    __half hv[4], lv[4];
#pragma unroll
    for (int q = 0; q < 4; q++) {
        hv[q] = __float2half_rn(o[q]);
        lv[q] = __float2half_rn(o[q] - __half2float(hv[q]));
    }
    *(uint2*)(g_hAh + (size_t)n * HID + c4) = *(uint2*)hv;
    *(uint2*)(g_hAl + (size_t)n * HID + c4) = *(uint2*)lv;
}

// ================= pipelined GEMM kernel with row offset =================
__global__ __launch_bounds__(256, 2) void mma_gemm_h(const __half* __restrict__ Ah,
                                                     const __half* __restrict__ Al,
                                                     const __half* __restrict__ Bh,
                                                     const __half* __restrict__ Bl,
                                                     const float* __restrict__ bias,
                                                     float* __restrict__ C,
                                                     int rowOff, int rowEnd, int ldc) {
    extern __shared__ __align__(16) char smem[];
    pipe_gemm_body(Ah, Al,
                   Bh + (size_t)blockIdx.x * 128 * 128, Bl + (size_t)blockIdx.x * 128 * 128,
                   bias, C, rowEnd, ldc, rowOff + blockIdx.y * 64, blockIdx.x * 128, smem);
}

// ================= GRU elementwise gates with row offset =================
__global__ __launch_bounds__(256) void gru_elem(const __half* __restrict__ hinh,
                                                const __half* __restrict__ hinl,
                                                __half* __restrict__ houth,
                                                __half* __restrict__ houtl,
                                                int step, int rowOff) {
    int gt = blockIdx.x * blockDim.x + threadIdx.x;
    int n = rowOff + (gt >> 5);
    int c4 = (gt & 31) * 4;
    int src = g_sel[(step - 1) * NN + n];
    const float* gi = g_G + (size_t)src * GH_M;
    const float* gh = g_GH + (size_t)n * GH_M;
    float4 gir = *(const float4*)(gi + c4);
    float4 giz = *(const float4*)(gi + 128 + c4);
    float4 gin = *(const float4*)(gi + 256 + c4);
    float4 ghr = *(const float4*)(gh + c4);
    float4 ghz = *(const float4*)(gh + 128 + c4);
    float4 ghn = *(const float4*)(gh + 256 + c4);
    uint2 hpu = *(const uint2*)(hinh + (size_t)n * HID + c4);
    uint2 hlu = *(const uint2*)(hinl + (size_t)n * HID + c4);
    __half* hph = (__half*)&hpu;
    __half* hpl = (__half*)&hlu;
    float o[4];
    float gir_a[4] = {gir.x, gir.y, gir.z, gir.w};
    float giz_a[4] = {giz.x, giz.y, giz.z, giz.w};
    float gin_a[4] = {gin.x, gin.y, gin.z, gin.w};
    float ghr_a[4] = {ghr.x, ghr.y, ghr.z, ghr.w};
    float ghz_a[4] = {ghz.x, ghz.y, ghz.z, ghz.w};
    float ghn_a[4] = {ghn.x, ghn.y, ghn.z, ghn.w};
#pragma unroll
    for (int q = 0; q < 4; q++) {
        float hp = __half2float(hph[q]) + __half2float(hpl[q]);
        float r = 1.0f / (1.0f + expf(-(gir_a[q] + ghr_a[q])));
        float z = 1.0f / (1.0f + expf(-(giz_a[q] + ghz_a[q])));
        o[q] = (1.0f - z) * tanhf(gin_a[q] + r * ghn_a[q]) + z * hp;
    }
    __half hv[4], lv[4];
#pragma unroll
    for (int q = 0; q < 4; q++) {
        hv[q] = __float2half_rn(o[q]);
        lv[q] = __float2half_rn(o[q] - __half2float(hv[q]));
    }
    *(uint2*)(houth + (size_t)n * HID + c4) = *(uint2*)hv;
    *(uint2*)(houtl + (size_t)n * HID + c4) = *(uint2*)lv;
}

// ---------------- host launch ----------------
extern "C" void kernel_launch(void* const* d_in, const int* in_sizes, int n_in,
                              void* d_out, int out_size) {
    const float* node_attr = (const float*)d_in[0];
    const int*   edge_idx  = (const int*)d_in[1];
    const float* W1   = (const float*)d_in[3];
    const float* b1   = (const float*)d_in[4];
    const float* W2   = (const float*)d_in[5];
    const float* b2   = (const float*)d_in[6];
    const float* Wih  = (const float*)d_in[7];
    const float* Whh  = (const float*)d_in[8];
    const float* bih  = (const float*)d_in[9];
    const float* bhh  = (const float*)d_in[10];
    const float* Wout = (const float*)d_in[11];
    const float* bout = (const float*)d_in[12];
    const float* noise = (const float*)d_in[13];
    float* out = (float*)d_out;
    const int* dst = edge_idx + (size_t)NN * DEG;

    float *pGH;
    __half *pHAh, *pHAl, *pHBh, *pHBl, *pWhhH, *pWhhL, *pWoutH, *pWoutL;
    cudaGetSymbolAddress((void**)&pGH, g_GH);
    cudaGetSymbolAddress((void**)&pHAh, g_hAh);
    cudaGetSymbolAddress((void**)&pHAl, g_hAl);
    cudaGetSymbolAddress((void**)&pHBh, g_hBh);
    cudaGetSymbolAddress((void**)&pHBl, g_hBl);
    cudaGetSymbolAddress((void**)&pWhhH, g_Whh_h);
    cudaGetSymbolAddress((void**)&pWhhL, g_Whh_l);
    cudaGetSymbolAddress((void**)&pWoutH, g_Wout_h);
    cudaGetSymbolAddress((void**)&pWoutL, g_Wout_l);

    static bool init_done = false;
    static cudaStream_t s1;
    static cudaEvent_t evPr, evW, evG1, evEnd;
    if (!init_done) {
        cudaFuncSetAttribute(proj_wih, cudaFuncAttributeMaxDynamicSharedMemorySize, PIPE_SMEM);
        cudaFuncSetAttribute(proj_score, cudaFuncAttributeMaxDynamicSharedMemorySize, SCORE_SMEM);
        cudaFuncSetAttribute(mma_gemm_h, cudaFuncAttributeMaxDynamicSharedMemorySize, PIPE_SMEM);
        cudaStreamCreateWithFlags(&s1, cudaStreamNonBlocking);
        cudaEventCreateWithFlags(&evPr, cudaEventDisableTiming);
        cudaEventCreateWithFlags(&evW, cudaEventDisableTiming);
        cudaEventCreateWithFlags(&evG1, cudaEventDisableTiming);
        cudaEventCreateWithFlags(&evEnd, cudaEventDisableTiming);
        init_done = true;
    }

    const int EBLK_H = HALF_N * 32 / 256;   // 1250

    // 1. merged weight prep + node_attr split (stream 0)
    prep_split<<<(PREP_TOTAL + SPLIT_TOTAL + 255) / 256, 256>>>(W1, b1, Wih, Whh, Wout,
                                                                node_attr);
    cudaEventRecord(evPr, 0);
    cudaStreamWaitEvent(s1, evPr, 0);

    // 2a. s1: scoring projection -> walk3
    proj_score<<<dim3(2, NBLK), 256, SCORE_SMEM, s1>>>(node_attr, NN);
    walk3<<<WALK_BLKS, 256, 0, s1>>>(dst, W2, b2, noise);
    cudaEventRecord(evW, s1);

    // 2b. stream 0: Wih projection -> gru0 -> full GEMM1
    proj_wih<<<dim3(3, NBLK), 256, PIPE_SMEM>>>(bih, NN);
    gru0<<<GRU0_BLKS, 256>>>(bhh);
    mma_gemm_h<<<dim3(3, NBLK), 256, PIPE_SMEM>>>(pHAh, pHAl, pWhhH, pWhhL, bhh, pGH,
                                                  0, NN, GH_M);
    cudaEventRecord(evG1, 0);

    // cross-join: 0 needs walk3; s1 needs GEMM1
    cudaStreamWaitEvent(0, evW, 0);
    cudaStreamWaitEvent(s1, evG1, 0);

    // 3. row-split GRU chains: half-1 on stream 0, half-2 on s1
    gru_elem<<<EBLK_H, 256>>>(pHAh, pHAl, pHBh, pHBl, 1, 0);
    mma_gemm_h<<<dim3(3, NBLK_H), 256, PIPE_SMEM>>>(pHBh, pHBl, pWhhH, pWhhL, bhh, pGH,
                                                    0, HALF_N, GH_M);
    gru_elem<<<EBLK_H, 256>>>(pHBh, pHBl, pHAh, pHAl, 2, 0);
    mma_gemm_h<<<dim3(3, NBLK_H), 256, PIPE_SMEM>>>(pHAh, pHAl, pWhhH, pWhhL, bhh, pGH,
                                                    0, HALF_N, GH_M);
    gru_elem<<<EBLK_H, 256>>>(pHAh, pHAl, pHBh, pHBl, 3, 0);
    mma_gemm_h<<<dim3(1, NBLK_H), 256, PIPE_SMEM>>>(pHBh, pHBl, pWoutH, pWoutL, bout, out,
                                                    0, HALF_N, HID);
    gru_elem<<<EBLK_H, 256, 0, s1>>>(pHAh, pHAl, pHBh, pHBl, 1, HALF_N);
    mma_gemm_h<<<dim3(3, NBLK_H), 256, PIPE_SMEM, s1>>>(pHBh, pHBl, pWhhH, pWhhL, bhh, pGH,
                                                        HALF_N, NN, GH_M);
    gru_elem<<<EBLK_H, 256, 0, s1>>>(pHBh, pHBl, pHAh, pHAl, 2, HALF_N);
    mma_gemm_h<<<dim3(3, NBLK_H), 256, PIPE_SMEM, s1>>>(pHAh, pHAl, pWhhH, pWhhL, bhh, pGH,
                                                        HALF_N, NN, GH_M);
    gru_elem<<<EBLK_H, 256, 0, s1>>>(pHAh, pHAl, pHBh, pHBl, 3, HALF_N);
    mma_gemm_h<<<dim3(1, NBLK_H), 256, PIPE_SMEM, s1>>>(pHBh, pHBl, pWoutH, pWoutL, bout, out,
                                                        HALF_N, NN, HID);
    cudaEventRecord(evEnd, s1);
    cudaStreamWaitEvent(0, evEnd, 0);
}

// round 17
// speedup vs baseline: 1.3793x; 1.0212x over previous
#include <cuda_runtime.h>
#include <cuda_fp16.h>
#include <cstdint>
#include <math.h>

#define NN      20000
#define DEG     16
#define TT      3
#define HID     128
#define EPS_SEL 0.01f
#define SC_M    256
#define GH_M    384
#define NBLK    313            // ceil(20000/64)
#define QTR_N   5000
#define NBLK_Q  79             // ceil(5000/64)
#define EBLK_Q  625            // 5000*32/256

// ---------------- device scratch ----------------
__device__ float g_SC [(size_t)NN * SC_M];
__device__ float g_G  [(size_t)NN * GH_M];
__device__ float g_GH [(size_t)NN * GH_M];
__device__ __align__(16) __half g_vh [(size_t)NN * 128];
__device__ __align__(16) __half g_vl [(size_t)NN * 128];
__device__ __align__(16) __half g_hAh[(size_t)NN * HID];
__device__ __align__(16) __half g_hAl[(size_t)NN * HID];
__device__ __align__(16) __half g_hBh[(size_t)NN * HID];
__device__ __align__(16) __half g_hBl[(size_t)NN * HID];
__device__ int   g_sel[TT * NN];
__device__ float g_Bsc_t[SC_M * 128];
__device__ float g_bias_sc[SC_M];
__device__ __align__(16) __half g_Wih_h[GH_M * 128], g_Wih_l[GH_M * 128];
__device__ __align__(16) __half g_Whh_h[GH_M * 128], g_Whh_l[GH_M * 128];
__device__ __align__(16) __half g_Wout_h[128 * 128], g_Wout_l[128 * 128];

__device__ __forceinline__ uint32_t smem_u32(const void* p) {
    uint32_t a;
    asm("{ .reg .u64 t; cvta.to.shared.u64 t, %1; cvt.u32.u64 %0, t; }" : "=r"(a) : "l"(p));
    return a;
}
__device__ __forceinline__ uint32_t f2tf32(float x) {
    uint32_t r;
    asm("cvt.rna.tf32.f32 %0, %1;" : "=r"(r) : "f"(x));
    return r;
}
#define CP16(dst, src) \
    asm volatile("cp.async.cg.shared.global [%0], [%1], 16;" :: "r"(dst), "l"(src))
#define CP_COMMIT() asm volatile("cp.async.commit_group;" ::: "memory")
#define CP_WAIT(n)  asm volatile("cp.async.wait_group %0;" :: "n"(n) : "memory")

// ---------------- merged weight prep + node_attr split ----------------
#define PREP_TOTAL (SC_M * 128 + 2 * GH_M * 128 + 128 * 128)   // 147456
#define SPLIT_TOTAL (NN * 128 / 4)                              // 640000
__global__ void prep_split(const float* __restrict__ W1, const float* __restrict__ b1,
                           const float* __restrict__ Wih, const float* __restrict__ Whh,
                           const float* __restrict__ Wout, const float* __restrict__ A) {
    int i = blockIdx.x * blockDim.x + threadIdx.x;
    if (i < PREP_TOTAL) {
        if (i < SC_M * 128) {
            int j = i / 128, k = i % 128;
            int s = j >> 6, m = j & 63;
            g_Bsc_t[i] = W1[(size_t)(s * 128 + k) * 64 + m];
            if (k == 0) g_bias_sc[j] = (j < 64) ? b1[j] : 0.0f;
            return;
        }
        int i2 = i - SC_M * 128;
        float w;
        __half *dh, *dl;
        if (i2 < GH_M * 128) { w = Wih[i2]; dh = g_Wih_h; dl = g_Wih_l; }
        else if (i2 < 2 * GH_M * 128) { i2 -= GH_M * 128; w = Whh[i2]; dh = g_Whh_h; dl = g_Whh_l; }
        else {
            i2 -= 2 * GH_M * 128;
            int n = i2 / 128, k = i2 % 128;
            w = Wout[(size_t)k * 128 + n];
            dh = g_Wout_h; dl = g_Wout_l;
        }
        __half hi = __float2half_rn(w);
        dh[i2] = hi;
        dl[i2] = __float2half_rn(w - __half2float(hi));
        return;
    }
    int t = i - PREP_TOTAL;
    if (t >= SPLIT_TOTAL) return;
    int e = t * 4;
    float4 a = *(const float4*)(A + e);
    float av[4] = {a.x, a.y, a.z, a.w};
    __half hv[4], lv[4];
#pragma unroll
    for (int q = 0; q < 4; q++) {
        hv[q] = __float2half_rn(av[q]);
        lv[q] = __float2half_rn(av[q] - __half2float(hv[q]));
    }
    *(uint2*)(g_vh + e) = *(uint2*)hv;
    *(uint2*)(g_vl + e) = *(uint2*)lv;
}

// ================= pipelined GEMM constants (2 x 64-k chunks, 2 stages) =================
#define HLDS 72
#define SA_H 0
#define SA_L (64 * HLDS * 2)
#define SB_H (2 * 64 * HLDS * 2)
#define SB_L (SB_H + 128 * HLDS * 2)
#define STAGE_BYTES (SB_L + 128 * HLDS * 2)      // 55296
#define PIPE_SMEM (2 * STAGE_BYTES)              // 110592

// pipelined fp16x2-split 64x128 GEMM tile body — 256 threads, 8 warps (2x4), warp tile 32x32
__device__ __forceinline__ void pipe_gemm_body(const __half* __restrict__ Ah,
                                               const __half* __restrict__ Al,
                                               const __half* __restrict__ bh,
                                               const __half* __restrict__ bl,
                                               const float* __restrict__ bias,
                                               float* __restrict__ C, int rows, int ldc,
                                               int rowBase, int colBase,
                                               char* smem) {
    uint32_t sb = smem_u32(smem);
    int tid = threadIdx.x;
    int lane = tid & 31;
    int wid = tid >> 5;
    int wm = wid >> 2, wn = wid & 3;   // 2 x 4 warps

#pragma unroll
    for (int kc = 0; kc < 2; kc++) {
        uint32_t stage = sb + kc * STAGE_BYTES;
        int kof = kc * 64;
#pragma unroll
        for (int i = 0; i < 2; i++) {
            int idx = tid + 256 * i;
            int r = idx >> 3, j = (idx & 7) * 8;
            int gr = rowBase + r;
            if (gr >= rows) gr = rows - 1;
            uint32_t off = (uint32_t)((r * HLDS + j) * 2);
            CP16(stage + SA_H + off, Ah + (size_t)gr * 128 + kof + j);
            CP16(stage + SA_L + off, Al + (size_t)gr * 128 + kof + j);
        }
#pragma unroll
        for (int i = 0; i < 4; i++) {
            int idx = tid + 256 * i;
            int r = idx >> 3, j = (idx & 7) * 8;
            uint32_t off = (uint32_t)((r * HLDS + j) * 2);
            CP16(stage + SB_H + off, bh + (size_t)r * 128 + kof + j);
            CP16(stage + SB_L + off, bl + (size_t)r * 128 + kof + j);
        }
        CP_COMMIT();
    }

    float acc[2][4][4];
#pragma unroll
    for (int mi = 0; mi < 2; mi++)
#pragma unroll
        for (int ni = 0; ni < 4; ni++)
#pragma unroll
            for (int q = 0; q < 4; q++) acc[mi][ni][q] = 0.0f;

    int a_r = lane & 15, a_c = (lane >> 4) * 8;
    int b_r = (lane & 7) + ((lane >> 4) << 3), b_c = ((lane >> 3) & 1) * 8;

#pragma unroll
    for (int kc = 0; kc < 2; kc++) {
        if (kc == 0) { CP_WAIT(1); } else { CP_WAIT(0); }
        __syncthreads();
        uint32_t stage = sb + kc * STAGE_BYTES;
        const uint32_t aOffT[3] = {stage + SA_H, stage + SA_H, stage + SA_L};
        const uint32_t bOffT[3] = {stage + SB_H, stage + SB_L, stage + SB_H};
#pragma unroll
        for (int term = 0; term < 3; term++) {
            uint32_t abase = aOffT[term], bbase = bOffT[term];
#pragma unroll
            for (int k0 = 0; k0 < 4; k0++) {
                int kk = k0 * 16;
                uint32_t af[2][4];
#pragma unroll
                for (int mi = 0; mi < 2; mi++) {
                    uint32_t addr = abase +
                        (uint32_t)(((wm * 32 + mi * 16 + a_r) * HLDS + kk + a_c) * 2);
                    asm volatile("ldmatrix.sync.aligned.m8n8.x4.shared.b16 {%0,%1,%2,%3}, [%4];"
                                 : "=r"(af[mi][0]), "=r"(af[mi][1]),
                                   "=r"(af[mi][2]), "=r"(af[mi][3]) : "r"(addr));
                }
                uint32_t bf[4][2];
#pragma unroll
                for (int nj = 0; nj < 2; nj++) {
                    uint32_t ba = bbase +
                        (uint32_t)(((wn * 32 + nj * 16 + b_r) * HLDS + kk + b_c) * 2);
                    uint32_t r0, r1, r2, r3;
                    asm volatile("ldmatrix.sync.aligned.m8n8.x4.shared.b16 {%0,%1,%2,%3}, [%4];"
                                 : "=r"(r0), "=r"(r1), "=r"(r2), "=r"(r3) : "r"(ba));
                    bf[2 * nj][0] = r0; bf[2 * nj][1] = r1;
                    bf[2 * nj + 1][0] = r2; bf[2 * nj + 1][1] = r3;
                }
#pragma unroll
                for (int mi = 0; mi < 2; mi++)
#pragma unroll
                    for (int ni = 0; ni < 4; ni++)
                        asm volatile(
                            "mma.sync.aligned.m16n8k16.row.col.f32.f16.f16.f32 "
                            "{%0,%1,%2,%3}, {%4,%5,%6,%7}, {%8,%9}, {%0,%1,%2,%3};"
                            : "+f"(acc[mi][ni][0]), "+f"(acc[mi][ni][1]),
                              "+f"(acc[mi][ni][2]), "+f"(acc[mi][ni][3])
                            : "r"(af[mi][0]), "r"(af[mi][1]), "r"(af[mi][2]), "r"(af[mi][3]),
                              "r"(bf[ni][0]), "r"(bf[ni][1]));
            }
        }
    }

    int cb = colBase + wn * 32;
#pragma unroll
    for (int mi = 0; mi < 2; mi++) {
        int rb = rowBase + wm * 32 + mi * 16;
#pragma unroll
        for (int ni = 0; ni < 4; ni++) {
            int r0 = rb + (lane >> 2);
            int c0 = cb + ni * 8 + (lane & 3) * 2;
            float bv0 = bias[c0], bv1 = bias[c0 + 1];
            if (r0 < rows)
                *(float2*)(C + (size_t)r0 * ldc + c0) =
                    make_float2(acc[mi][ni][0] + bv0, acc[mi][ni][1] + bv1);
            if (r0 + 8 < rows)
                *(float2*)(C + (size_t)(r0 + 8) * ldc + c0) =
                    make_float2(acc[mi][ni][2] + bv0, acc[mi][ni][3] + bv1);
        }
    }
}

// ================= Wih projection kernel =================
__global__ __launch_bounds__(256, 2) void proj_wih(const float* __restrict__ bih, int rows) {
    extern __shared__ __align__(16) char smem[];
    int bx = blockIdx.x;
    pipe_gemm_body(g_vh, g_vl,
                   g_Wih_h + (size_t)bx * 128 * 128, g_Wih_l + (size_t)bx * 128 * 128,
                   bih, g_G, rows, GH_M, blockIdx.y * 64, bx * 128, smem);
}

// ================= scoring projection kernel (tf32) =================
#define SLDS 132
#define SCORE_SMEM ((64 + 128) * SLDS * 4)
__global__ __launch_bounds__(256, 2) void proj_score(const float* __restrict__ A, int rows) {
    extern __shared__ __align__(16) char smem[];
    int tid = threadIdx.x;
    int lane = tid & 31;
    int wid = tid >> 5;
    int rowBase = blockIdx.y * 64;

    float* As = (float*)smem;
    float* Bs = As + 64 * SLDS;
    int colBase = blockIdx.x * 128;
    for (int c = tid; c < 2048; c += 256) {
        int r = c >> 5, k = (c & 31) * 4;
        int gr = rowBase + r;
        float4 a = make_float4(0.f, 0.f, 0.f, 0.f);
        if (gr < rows) a = *(const float4*)(A + (size_t)gr * 128 + k);
        *(float4*)(As + r * SLDS + k) = a;
    }
    for (int c = tid; c < 4096; c += 256) {
        int r = c >> 5, k = (c & 31) * 4;
        *(float4*)(Bs + r * SLDS + k) =
            *(const float4*)(g_Bsc_t + (size_t)(colBase + r) * 128 + k);
    }
    __syncthreads();

    int wm = wid >> 1, wn = wid & 1;
    int m0 = wm * 16, n0 = wn * 64;
    int gid = lane >> 2, tig = lane & 3;
    float acc[8][4];
#pragma unroll
    for (int ni = 0; ni < 8; ni++)
#pragma unroll
        for (int q = 0; q < 4; q++) acc[ni][q] = 0.0f;

#pragma unroll
    for (int k0 = 0; k0 < 16; k0++) {
        int kk = k0 * 8;
        float av[4] = {As[(m0 + gid) * SLDS + kk + tig],
                       As[(m0 + gid + 8) * SLDS + kk + tig],
                       As[(m0 + gid) * SLDS + kk + tig + 4],
                       As[(m0 + gid + 8) * SLDS + kk + tig + 4]};
        uint32_t ah[4], al[4];
#pragma unroll
        for (int q = 0; q < 4; q++) {
            ah[q] = f2tf32(av[q]);
            al[q] = f2tf32(av[q] - __uint_as_float(ah[q]));
        }
#pragma unroll
        for (int nf = 0; nf < 8; nf++) {
            float b0 = Bs[(n0 + nf * 8 + gid) * SLDS + kk + tig];
            float b1 = Bs[(n0 + nf * 8 + gid) * SLDS + kk + tig + 4];
            uint32_t bh0 = f2tf32(b0), bh1 = f2tf32(b1);
            uint32_t bl0 = f2tf32(b0 - __uint_as_float(bh0));
            uint32_t bl1 = f2tf32(b1 - __uint_as_float(bh1));
            asm volatile(
                "mma.sync.aligned.m16n8k8.row.col.f32.tf32.tf32.f32 "
                "{%0,%1,%2,%3}, {%4,%5,%6,%7}, {%8,%9}, {%0,%1,%2,%3};"
                : "+f"(acc[nf][0]), "+f"(acc[nf][1]), "+f"(acc[nf][2]), "+f"(acc[nf][3])
                : "r"(ah[0]), "r"(ah[1]), "r"(ah[2]), "r"(ah[3]), "r"(bh0), "r"(bh1));
            asm volatile(
                "mma.sync.aligned.m16n8k8.row.col.f32.tf32.tf32.f32 "
                "{%0,%1,%2,%3}, {%4,%5,%6,%7}, {%8,%9}, {%0,%1,%2,%3};"
                : "+f"(acc[nf][0]), "+f"(acc[nf][1]), "+f"(acc[nf][2]), "+f"(acc[nf][3])
                : "r"(ah[0]), "r"(ah[1]), "r"(ah[2]), "r"(ah[3]), "r"(bl0), "r"(bl1));
            asm volatile(
                "mma.sync.aligned.m16n8k8.row.col.f32.tf32.tf32.f32 "
                "{%0,%1,%2,%3}, {%4,%5,%6,%7}, {%8,%9}, {%0,%1,%2,%3};"
                : "+f"(acc[nf][0]), "+f"(acc[nf][1]), "+f"(acc[nf][2]), "+f"(acc[nf][3])
                : "r"(al[0]), "r"(al[1]), "r"(al[2]), "r"(al[3]), "r"(bh0), "r"(bh1));
        }
    }
    int rb = rowBase + m0;
#pragma unroll
    for (int nf = 0; nf < 8; nf++) {
        int c0 = colBase + n0 + nf * 8 + tig * 2;
        float bv0 = g_bias_sc[c0], bv1 = g_bias_sc[c0 + 1];
#pragma unroll
        for (int half = 0; half < 2; half++) {
            int r0 = rb + gid + half * 8;
            if (r0 >= rows) continue;
            *(float2*)(g_SC + (size_t)r0 * SC_M + c0) =
                make_float2(acc[nf][2 * half] + bv0, acc[nf][2 * half + 1] + bv1);
        }
    }
}

// ================= walk (3 steps) — unchanged =================
#define WALK_BLKS ((NN * 32 + 255) / 256)
__global__ __launch_bounds__(256) void walk3(const int* __restrict__ dst,
                                             const float* __restrict__ W2,
                                             const float* __restrict__ b2p,
                                             const float* __restrict__ noise) {
    const unsigned FULL = 0xFFFFFFFFu;
    int tid = threadIdx.x;
    int gwarp = (blockIdx.x * 256 + tid) >> 5;
    int lane = tid & 31;
    int wz = tid >> 5;
    __shared__ float s_logp[8][16];
    if (gwarp >= NN) return;
    int n = gwarp;
    int q = lane & 15;
    int h = lane >> 4;

    float4 bse = *(const float4*)(g_SC + (size_t)n * SC_M + q * 4);
    float4 w2 = *(const float4*)(W2 + q * 4);
    float b2 = b2p[0];
    int cur = n;

#pragma unroll
    for (int t = 0; t < TT; t++) {
        const int* nb = dst + (size_t)cur * DEG;
        const int slot = (1 + t) * 64;
#pragma unroll
        for (int it = 0; it < 8; it++) {
            int d = it * 2 + h;
            int cand = nb[d];
            float4 c = *(const float4*)(g_SC + (size_t)cand * SC_M + slot + q * 4);
            float s = fmaxf(bse.x + c.x, 0.f) * w2.x + fmaxf(bse.y + c.y, 0.f) * w2.y +
                      fmaxf(bse.z + c.z, 0.f) * w2.z + fmaxf(bse.w + c.w, 0.f) * w2.w;
#pragma unroll
            for (int off = 8; off >= 1; off >>= 1)
                s += __shfl_xor_sync(FULL, s, off);
            if (q == 0) s_logp[wz][d] = s + b2;
        }
        __syncwarp();
        float lp = (lane < DEG) ? s_logp[wz][lane] : -1e38f;
        float m = lp;
#pragma unroll
        for (int off = 8; off >= 1; off >>= 1)
            m = fmaxf(m, __shfl_xor_sync(FULL, m, off));
        float e = (lane < DEG) ? expf(lp - m) : 0.0f;
        float ssum = e;
#pragma unroll
        for (int off = 8; off >= 1; off >>= 1)
            ssum += __shfl_xor_sync(FULL, ssum, off);
        float norm = m + logf(ssum);
        float p = (lane < DEG)
                      ? expf(lp - norm) + EPS_SEL * noise[((size_t)t * NN + n) * DEG + lane]
                      : -1e38f;
        float bv = p;
        int bi = lane;
#pragma unroll
        for (int off = 8; off >= 1; off >>= 1) {
            float ov = __shfl_xor_sync(FULL, bv, off);
            int oi = __shfl_xor_sync(FULL, bi, off);
            if (ov > bv || (ov == bv && oi < bi)) { bv = ov; bi = oi; }
        }
        int bsel = __shfl_sync(FULL, bi, 0);
        int csel = nb[bsel];
        float4 c = *(const float4*)(g_SC + (size_t)csel * SC_M + slot + q * 4);
        bse.x += c.x; bse.y += c.y; bse.z += c.z; bse.w += c.w;
        cur = csel;
        if (lane == 0) g_sel[t * NN + n] = csel;
        __syncwarp();
    }
}

// ================= gru0 (h_prev = 0) with row offset =================
__global__ __launch_bounds__(256) void gru0(const float* __restrict__ bhh, int rowOff) {
    int gt = blockIdx.x * 256 + threadIdx.x;
    int n = rowOff + (gt >> 5);
    int c4 = (gt & 31) * 4;
    const float* gi = g_G + (size_t)n * GH_M;
    float4 gir = *(const float4*)(gi + c4);
    float4 giz = *(const float4*)(gi + 128 + c4);
    float4 gin = *(const float4*)(gi + 256 + c4);
    float4 br = *(const float4*)(bhh + c4);
    float4 bz = *(const float4*)(bhh + 128 + c4);
    float4 bn = *(const float4*)(bhh + 256 + c4);
    float o[4];
    {
        float r = 1.0f / (1.0f + expf(-(gir.x + br.x)));
        float z = 1.0f / (1.0f + expf(-(giz.x + bz.x)));
        o[0] = (1.0f - z) * tanhf(gin.x + r * bn.x);
    }
    {
        float r = 1.0f / (1.0f + expf(-(gir.y + br.y)));
        float z = 1.0f / (1.0f + expf(-(giz.y + bz.y)));
        o[1] = (1.0f - z) * tanhf(gin.y + r * bn.y);
    }
    {
        float r = 1.0f / (1.0f + expf(-(gir.z + br.z)));
        float z = 1.0f / (1.0f + expf(-(giz.z + bz.z)));
        o[2] = (1.0f - z) * tanhf(gin.z + r * bn.z);
    }
    {
        float r = 1.0f / (1.0f + expf(-(gir.w + br.w)));
        float z = 1.0f / (1.0f + expf(-(giz.w + bz.w)));
        o[3] = (1.0f - z) * tanhf(gin.w + r * bn.w);
    }
    __half hv[4], lv[4];
#pragma unroll
    for (int q = 0; q < 4; q++) {
        hv[q] = __float2half_rn(o[q]);
        lv[q] = __float2half_rn(o[q] - __half2float(hv[q]));
    }
    *(uint2*)(g_hAh + (size_t)n * HID + c4) = *(uint2*)hv;
    *(uint2*)(g_hAl + (size_t)n * HID + c4) = *(uint2*)lv;
}

// ================= pipelined GEMM kernel with row offset =================
__global__ __launch_bounds__(256, 2) void mma_gemm_h(const __half* __restrict__ Ah,
                                                     const __half* __restrict__ Al,
                                                     const __half* __restrict__ Bh,
                                                     const __half* __restrict__ Bl,
                                                     const float* __restrict__ bias,
                                                     float* __restrict__ C,
                                                     int rowOff, int rowEnd, int ldc) {
    extern __shared__ __align__(16) char smem[];
    pipe_gemm_body(Ah, Al,
                   Bh + (size_t)blockIdx.x * 128 * 128, Bl + (size_t)blockIdx.x * 128 * 128,
                   bias, C, rowEnd, ldc, rowOff + blockIdx.y * 64, blockIdx.x * 128, smem);
}

// ================= GRU elementwise gates with row offset =================
__global__ __launch_bounds__(256) void gru_elem(const __half* __restrict__ hinh,
                                                const __half* __restrict__ hinl,
                                                __half* __restrict__ houth,
                                                __half* __restrict__ houtl,
                                                int step, int rowOff) {
    int gt = blockIdx.x * blockDim.x + threadIdx.x;
    int n = rowOff + (gt >> 5);
    int c4 = (gt & 31) * 4;
    int src = g_sel[(step - 1) * NN + n];
    const float* gi = g_G + (size_t)src * GH_M;
    const float* gh = g_GH + (size_t)n * GH_M;
    float4 gir = *(const float4*)(gi + c4);
    float4 giz = *(const float4*)(gi + 128 + c4);
    float4 gin = *(const float4*)(gi + 256 + c4);
    float4 ghr = *(const float4*)(gh + c4);
    float4 ghz = *(const float4*)(gh + 128 + c4);
    float4 ghn = *(const float4*)(gh + 256 + c4);
    uint2 hpu = *(const uint2*)(hinh + (size_t)n * HID + c4);
    uint2 hlu = *(const uint2*)(hinl + (size_t)n * HID + c4);
    __half* hph = (__half*)&hpu;
    __half* hpl = (__half*)&hlu;
    float o[4];
    float gir_a[4] = {gir.x, gir.y, gir.z, gir.w};
    float giz_a[4] = {giz.x, giz.y, giz.z, giz.w};
    float gin_a[4] = {gin.x, gin.y, gin.z, gin.w};
    float ghr_a[4] = {ghr.x, ghr.y, ghr.z, ghr.w};
    float ghz_a[4] = {ghz.x, ghz.y, ghz.z, ghz.w};
    float ghn_a[4] = {ghn.x, ghn.y, ghn.z, ghn.w};
#pragma unroll
    for (int q = 0; q < 4; q++) {
        float hp = __half2float(hph[q]) + __half2float(hpl[q]);
        float r = 1.0f / (1.0f + expf(-(gir_a[q] + ghr_a[q])));
        float z = 1.0f / (1.0f + expf(-(giz_a[q] + ghz_a[q])));
        o[q] = (1.0f - z) * tanhf(gin_a[q] + r * ghn_a[q]) + z * hp;
    }
    __half hv[4], lv[4];
#pragma unroll
    for (int q = 0; q < 4; q++) {
        hv[q] = __float2half_rn(o[q]);
        lv[q] = __float2half_rn(o[q] - __half2float(hv[q]));
    }
    *(uint2*)(houth + (size_t)n * HID + c4) = *(uint2*)hv;
    *(uint2*)(houtl + (size_t)n * HID + c4) = *(uint2*)lv;
}

// ---------------- host launch ----------------
extern "C" void kernel_launch(void* const* d_in, const int* in_sizes, int n_in,
                              void* d_out, int out_size) {
    const float* node_attr = (const float*)d_in[0];
    const int*   edge_idx  = (const int*)d_in[1];
    const float* W1   = (const float*)d_in[3];
    const float* b1   = (const float*)d_in[4];
    const float* W2   = (const float*)d_in[5];
    const float* b2   = (const float*)d_in[6];
    const float* Wih  = (const float*)d_in[7];
    const float* Whh  = (const float*)d_in[8];
    const float* bih  = (const float*)d_in[9];
    const float* bhh  = (const float*)d_in[10];
    const float* Wout = (const float*)d_in[11];
    const float* bout = (const float*)d_in[12];
    const float* noise = (const float*)d_in[13];
    float* out = (float*)d_out;
    const int* dst = edge_idx + (size_t)NN * DEG;

    float *pGH;
    __half *pHAh, *pHAl, *pHBh, *pHBl, *pWhhH, *pWhhL, *pWoutH, *pWoutL;
    cudaGetSymbolAddress((void**)&pGH, g_GH);
    cudaGetSymbolAddress((void**)&pHAh, g_hAh);
    cudaGetSymbolAddress((void**)&pHAl, g_hAl);
    cudaGetSymbolAddress((void**)&pHBh, g_hBh);
    cudaGetSymbolAddress((void**)&pHBl, g_hBl);
    cudaGetSymbolAddress((void**)&pWhhH, g_Whh_h);
    cudaGetSymbolAddress((void**)&pWhhL, g_Whh_l);
    cudaGetSymbolAddress((void**)&pWoutH, g_Wout_h);
    cudaGetSymbolAddress((void**)&pWoutL, g_Wout_l);

    static bool init_done = false;
    static cudaStream_t st[4];   // st[0] = legacy stream alias (use 0), st[1..3] created
    static cudaEvent_t evPr, evW, evPw, evQ1, evQ2, evQ3;
    if (!init_done) {
        cudaFuncSetAttribute(proj_wih, cudaFuncAttributeMaxDynamicSharedMemorySize, PIPE_SMEM);
        cudaFuncSetAttribute(proj_score, cudaFuncAttributeMaxDynamicSharedMemorySize, SCORE_SMEM);
        cudaFuncSetAttribute(mma_gemm_h, cudaFuncAttributeMaxDynamicSharedMemorySize, PIPE_SMEM);
        st[0] = 0;
        for (int i = 1; i < 4; i++) cudaStreamCreateWithFlags(&st[i], cudaStreamNonBlocking);
        cudaEventCreateWithFlags(&evPr, cudaEventDisableTiming);
        cudaEventCreateWithFlags(&evW, cudaEventDisableTiming);
        cudaEventCreateWithFlags(&evPw, cudaEventDisableTiming);
        cudaEventCreateWithFlags(&evQ1, cudaEventDisableTiming);
        cudaEventCreateWithFlags(&evQ2, cudaEventDisableTiming);
        cudaEventCreateWithFlags(&evQ3, cudaEventDisableTiming);
        init_done = true;
    }

    // 1. merged weight prep + node_attr split (stream 0)
    prep_split<<<(PREP_TOTAL + SPLIT_TOTAL + 255) / 256, 256>>>(W1, b1, Wih, Whh, Wout,
                                                                node_attr);
    cudaEventRecord(evPr, 0);
    cudaStreamWaitEvent(st[1], evPr, 0);

    // 2a. st[1]: scoring projection -> walk3
    proj_score<<<dim3(2, NBLK), 256, SCORE_SMEM, st[1]>>>(node_attr, NN);
    walk3<<<WALK_BLKS, 256, 0, st[1]>>>(dst, W2, b2, noise);
    cudaEventRecord(evW, st[1]);

    // 2b. stream 0: Wih projection; fan out per-quarter gru0 + GEMM1
    proj_wih<<<dim3(3, NBLK), 256, PIPE_SMEM>>>(bih, NN);
    cudaEventRecord(evPw, 0);
    cudaStreamWaitEvent(st[2], evPw, 0);
    cudaStreamWaitEvent(st[3], evPw, 0);
    // st[1] gets evPw implicitly ordered after its own work? NO — needs explicit wait:
    cudaStreamWaitEvent(st[1], evPw, 0);

    for (int q = 0; q < 4; q++) {
        cudaStream_t s = st[q];
        int ro = q * QTR_N;
        gru0<<<EBLK_Q, 256, 0, s>>>(bhh, ro);
        mma_gemm_h<<<dim3(3, NBLK_Q), 256, PIPE_SMEM, s>>>(pHAh, pHAl, pWhhH, pWhhL, bhh,
                                                           pGH, ro, ro + QTR_N, GH_M);
    }
    // all quarter chains need walk3's g_sel
    cudaStreamWaitEvent(0, evW, 0);
    cudaStreamWaitEvent(st[2], evW, 0);
    cudaStreamWaitEvent(st[3], evW, 0);
    // st[1] already ordered after walk3 (same stream)

    // 3. quarter GRU chains
    for (int q = 0; q < 4; q++) {
        cudaStream_t s = st[q];
        int ro = q * QTR_N;
        gru_elem<<<EBLK_Q, 256, 0, s>>>(pHAh, pHAl, pHBh, pHBl, 1, ro);
        mma_gemm_h<<<dim3(3, NBLK_Q), 256, PIPE_SMEM, s>>>(pHBh, pHBl, pWhhH, pWhhL, bhh,
                                                           pGH, ro, ro + QTR_N, GH_M);
        gru_elem<<<EBLK_Q, 256, 0, s>>>(pHBh, pHBl, pHAh, pHAl, 2, ro);
        mma_gemm_h<<<dim3(3, NBLK_Q), 256, PIPE_SMEM, s>>>(pHAh, pHAl, pWhhH, pWhhL, bhh,
                                                           pGH, ro, ro + QTR_N, GH_M);
        gru_elem<<<EBLK_Q, 256, 0, s>>>(pHAh, pHAl, pHBh, pHBl, 3, ro);
        mma_gemm_h<<<dim3(1, NBLK_Q), 256, PIPE_SMEM, s>>>(pHBh, pHBl, pWoutH, pWoutL, bout,
                                                           out, ro, ro + QTR_N, HID);
    }
    cudaEventRecord(evQ1, st[1]);
    cudaEventRecord(evQ2, st[2]);
    cudaEventRecord(evQ3, st[3]);
    cudaStreamWaitEvent(0, evQ1, 0);
    cudaStreamWaitEvent(0, evQ2, 0);
    cudaStreamWaitEvent(0, evQ3, 0);
}